// round 5
// baseline (speedup 1.0000x reference)
#include <cuda_runtime.h>
#include <cuda_bf16.h>
#include <cstdint>

#define NN 20000
#define NE 640000
#define P_PATH 512
#define S_SUB 64
#define DHID 256

typedef unsigned long long ull;

// ---------------- scratch (static device globals; no allocation) ----------------
static __device__ __align__(16) float g_agg[NN * 128];
static __device__ __align__(16) float g_part[NN * 256];
static __device__ __align__(16) float g_h1[NN * 24];
static __device__ __align__(16) float g_h2[NN * 64];
static __device__ __align__(16) float g_h3[NN * 128];
static __device__ __align__(16) float g_h4[NN * 256];
static __device__ int g_deg[NN];
static __device__ int g_off[NN + 1];
static __device__ int g_cur[NN];
static __device__ int g_srcs[NE];
static __device__ float g_c[3 * 1024];
static __device__ __align__(16) float g_r0[3 * P_PATH * 256];
static __device__ __align__(16) float g_gates[3 * P_PATH * 1024];
static __device__ __align__(16) float g_q1[3 * P_PATH * 256];
static __device__ __align__(16) float g_r1[3 * P_PATH * 256];
static __device__ float g_xg[P_PATH];

__device__ __forceinline__ float sigm(float x) { return 1.f / (1.f + __expf(-x)); }

__device__ __forceinline__ void ffma2(ull& acc, ull a, ull b) {
    asm("fma.rn.f32x2 %0, %1, %2, %0;" : "+l"(acc) : "l"(a), "l"(b));
}
__device__ __forceinline__ float hsum2(ull v) {
    return __uint_as_float((unsigned)v) + __uint_as_float((unsigned)(v >> 32));
}

__device__ __forceinline__ void mbar_wait(uint32_t mbar, int phase) {
    asm volatile(
        "{\n\t"
        ".reg .pred P1;\n\t"
        "WAIT_LOOP_%=:\n\t"
        "mbarrier.try_wait.parity.acquire.cta.shared::cta.b64 P1, [%0], %1, 0x989680;\n\t"
        "@P1 bra.uni WAIT_DONE_%=;\n\t"
        "bra.uni WAIT_LOOP_%=;\n\t"
        "WAIT_DONE_%=:\n\t"
        "}" ::"r"(mbar),
        "r"(phase)
        : "memory");
}

// ---------------- CSR build ----------------
__global__ void hist_kernel(const int* __restrict__ dst, int* __restrict__ deg, int E) {
    int e = blockIdx.x * blockDim.x + threadIdx.x;
    if (e < E) atomicAdd(&deg[dst[e]], 1);
}

__global__ void scan_kernel(const int* __restrict__ deg, int* __restrict__ off,
                            int* __restrict__ cur) {
    __shared__ int part[1024];
    int t = threadIdx.x;
    const int CH = (NN + 1023) / 1024;
    int start = t * CH;
    int end = min(start + CH, NN);
    int s = 0;
    for (int i = start; i < end; i++) s += deg[i];
    part[t] = s;
    __syncthreads();
    for (int o = 1; o < 1024; o <<= 1) {
        int v = (t >= o) ? part[t - o] : 0;
        __syncthreads();
        part[t] += v;
        __syncthreads();
    }
    int base = (t > 0) ? part[t - 1] : 0;
    for (int i = start; i < end; i++) {
        off[i] = base;
        cur[i] = base;
        base += deg[i];
    }
    if (t == 1023) off[NN] = part[1023];
}

__global__ void bucket_kernel(const int* __restrict__ src, const int* __restrict__ dst,
                              int* __restrict__ cur, int* __restrict__ srcs, int E) {
    int e = blockIdx.x * blockDim.x + threadIdx.x;
    if (e < E) {
        int p = atomicAdd(&cur[dst[e]], 1);
        srcs[p] = src[e];
    }
}

// ---------------- TMA-gather aggregation: out[i] = h[i] + sum_{j->i} h[j] ----------------
// Rows are DD*4 bytes (16B multiple). Per block: NPB nodes, double-buffered BATCH-edge
// TMA bulk copies into smem, 128 consumer threads accumulate.
template <int DD, int BATCH, int NPB>
__global__ void agg_tma(const float* __restrict__ h, const int* __restrict__ off,
                        const int* __restrict__ srcs, float* __restrict__ outp) {
    constexpr int ROWB = DD * 4;       // bytes per row
    constexpr int CPR = ROWB / 16;     // float4 chunks per row
    constexpr int T = 128;
    constexpr int G = T / CPR;         // edges consumed in parallel
    extern __shared__ __align__(16) char sm_raw[];
    char* bufs = sm_raw;                                        // 2 * BATCH * ROWB
    float4* comb = (float4*)(sm_raw + 2 * BATCH * ROWB + 16);   // T float4
    int tid = threadIdx.x;
    uint32_t sbase;
    asm("{ .reg .u64 t; cvta.to.shared.u64 t, %1; cvt.u32.u64 %0, t; }"
        : "=r"(sbase)
        : "l"(sm_raw));
    uint32_t barA[2] = {sbase + 2u * BATCH * ROWB, sbase + 2u * BATCH * ROWB + 8u};
    if (tid == 0) {
        asm volatile("mbarrier.init.shared.b64 [%0], 1;" ::"r"(barA[0]) : "memory");
        asm volatile("mbarrier.init.shared.b64 [%0], 1;" ::"r"(barA[1]) : "memory");
    }
    __syncthreads();
    int ph[2] = {0, 0};
    int g = tid / CPR, c = tid % CPR;
    const float4* h4 = (const float4*)h;
    float4* o4 = (float4*)outp;

    for (int ni = 0; ni < NPB; ni++) {
        int node = blockIdx.x * NPB + ni;
        if (node >= NN) break;
        int s0 = off[node];
        int len = off[node + 1] - s0;
        int nb = (len + BATCH - 1) / BATCH;
        float4 acc = {0.f, 0.f, 0.f, 0.f};

        if (tid == 0 && nb > 0) {  // issue batch 0 into buffer 0
            int cnt = min(BATCH, len);
            asm volatile("mbarrier.arrive.expect_tx.shared.b64 _, [%0], %1;" ::"r"(barA[0]),
                         "r"((unsigned)(cnt * ROWB))
                         : "memory");
            for (int i = 0; i < cnt; i++) {
                const char* src = (const char*)(h + (size_t)srcs[s0 + i] * DD);
                asm volatile(
                    "cp.async.bulk.shared::cluster.global.mbarrier::complete_tx::bytes "
                    "[%0], [%1], %2, [%3];" ::"r"(sbase + (unsigned)(i * ROWB)),
                    "l"(src), "r"(ROWB), "r"(barA[0])
                    : "memory");
            }
        }
        for (int b = 0; b < nb; b++) {
            int u = b & 1;
            if (tid == 0 && b + 1 < nb) {  // issue batch b+1 into the other buffer
                int u2 = (b + 1) & 1;
                int base = s0 + (b + 1) * BATCH;
                int cnt = min(BATCH, len - (b + 1) * BATCH);
                asm volatile("mbarrier.arrive.expect_tx.shared.b64 _, [%0], %1;" ::"r"(barA[u2]),
                             "r"((unsigned)(cnt * ROWB))
                             : "memory");
                uint32_t d0 = sbase + (unsigned)(u2 * BATCH * ROWB);
                for (int i = 0; i < cnt; i++) {
                    const char* src = (const char*)(h + (size_t)srcs[base + i] * DD);
                    asm volatile(
                        "cp.async.bulk.shared::cluster.global.mbarrier::complete_tx::bytes "
                        "[%0], [%1], %2, [%3];" ::"r"(d0 + (unsigned)(i * ROWB)),
                        "l"(src), "r"(ROWB), "r"(barA[u2])
                        : "memory");
                }
            }
            mbar_wait(barA[u], ph[u]);
            ph[u] ^= 1;
            int cnt = min(BATCH, len - b * BATCH);
            const float4* bf = (const float4*)(bufs + (size_t)u * BATCH * ROWB);
            if (g < G) {
                for (int e = g; e < cnt; e += G) {
                    float4 v = bf[e * CPR + c];
                    acc.x += v.x;
                    acc.y += v.y;
                    acc.z += v.z;
                    acc.w += v.w;
                }
            }
            __syncthreads();  // buffer u fully consumed before reuse
        }
        comb[tid] = acc;
        __syncthreads();
        if (tid < CPR) {
            float4 s = h4[(size_t)node * CPR + tid];
#pragma unroll
            for (int gg = 0; gg < G; gg++) {
                float4 v = comb[gg * CPR + tid];
                s.x += v.x;
                s.y += v.y;
                s.z += v.z;
                s.w += v.w;
            }
            o4[(size_t)node * CPR + tid] = s;
        }
        __syncthreads();
    }
}

// ---------------- sliced LDG aggregation (layer 1, D=8) ----------------
template <int D, int NS>
__global__ void aggregate_sliced(const float* __restrict__ h, const int* __restrict__ off,
                                 const int* __restrict__ srcs, float* __restrict__ part) {
    constexpr int C = D / 4;
    int idx = blockIdx.x * blockDim.x + threadIdx.x;
    if (idx >= NN * C * NS) return;
    int slice = idx / (NN * C);
    int rem = idx - slice * NN * C;
    int node = rem / C;
    int c = rem - node * C;
    const float4* hp = reinterpret_cast<const float4*>(h);
    int s0 = off[node], s1 = off[node + 1];
    int len = s1 - s0;
    int a = s0 + (len * slice) / NS;
    int b = s0 + (len * (slice + 1)) / NS;
    float4 acc = {0.f, 0.f, 0.f, 0.f};
#pragma unroll 4
    for (int j = a; j < b; j++) {
        int s = __ldg(&srcs[j]);
        float4 v = hp[(size_t)s * C + c];
        acc.x += v.x;
        acc.y += v.y;
        acc.z += v.z;
        acc.w += v.w;
    }
    reinterpret_cast<float4*>(part)[(size_t)slice * NN * C + (size_t)node * C + c] = acc;
}

// ---------------- GIN GEMM: out = relu(xin_sum @ W^T + b), f32x2 FMA ----------------
template <int K, int N, int NP, int T, int RPB, int NSLICE>
__global__ void gemm_relu(const float* __restrict__ xin, const float* __restrict__ part,
                          const float* __restrict__ W, const float* __restrict__ b,
                          float* __restrict__ out, int nrows) {
    constexpr int LDK = K + 4;
    constexpr int G = T / NP;
    constexpr int RPT = RPB / G;
    extern __shared__ float sm[];
    float* sW = sm;            // N * LDK
    float* sR = sm + N * LDK;  // RPB * K
    int tid = threadIdx.x;
    for (int i = tid; i < K * N; i += T) {
        int j = i / K, k = i - j * K;
        sW[j * LDK + k] = W[i];
    }
    int row0 = blockIdx.x * RPB;
    for (int i = tid; i < RPB * K; i += T) {
        int r = i / K, k = i - r * K;
        int row = row0 + r;
        float v = 0.f;
        if (row < nrows) {
            v = xin[(size_t)row * K + k];
            if (NSLICE > 0) {
#pragma unroll
                for (int s = 0; s < NSLICE; s++) v += part[((size_t)s * NN + row) * K + k];
            }
        }
        sR[i] = v;
    }
    __syncthreads();
    int j = tid % NP;
    int rg = tid / NP;
    if (j < N) {
        ull acc2[RPT];
#pragma unroll
        for (int t = 0; t < RPT; t++) acc2[t] = 0ull;
        const ull* wp = reinterpret_cast<const ull*>(&sW[j * LDK]);
        for (int k = 0; k < K; k += 4) {
            ull w01 = wp[k / 2];
            ull w23 = wp[k / 2 + 1];
#pragma unroll
            for (int t = 0; t < RPT; t++) {
                const ull* sp = reinterpret_cast<const ull*>(&sR[(rg + t * G) * K]);
                ffma2(acc2[t], w01, sp[k / 2]);
                ffma2(acc2[t], w23, sp[k / 2 + 1]);
            }
        }
        float bj = b[j];
#pragma unroll
        for (int t = 0; t < RPT; t++) {
            int row = row0 + rg + t * G;
            if (row < nrows) out[(size_t)row * N + j] = fmaxf(hsum2(acc2[t]) + bj, 0.f);
        }
    }
}

// c[k,j] = bih+bhh + sum_d q0[k,d]*(Wih[k,j,d] + Whh[k,j,d]); q0 from biases
__global__ void s2s_cvec(const float* __restrict__ Wih, const float* __restrict__ Whh,
                         const float* __restrict__ bih, const float* __restrict__ bhh,
                         float* __restrict__ c) {
    int k = blockIdx.y;
    int tid = threadIdx.x;
    int j = blockIdx.x * 256 + tid;
    __shared__ __align__(16) float sq[256];
    {
        const float* bi = bih + k * 1024;
        const float* bh = bhh + k * 1024;
        float gi = bi[tid] + bh[tid];
        float gg = bi[512 + tid] + bh[512 + tid];
        float go = bi[768 + tid] + bh[768 + tid];
        float cs = sigm(gi) * tanhf(gg);
        sq[tid] = sigm(go) * tanhf(cs);
    }
    __syncthreads();
    const float* wi = Wih + ((size_t)k * 1024 + j) * 512;
    const float* wh = Whh + ((size_t)k * 1024 + j) * 256;
    float acc = bih[k * 1024 + j] + bhh[k * 1024 + j];
    for (int d = 0; d < 256; d += 4) {
        float4 a = *reinterpret_cast<const float4*>(wi + d);
        float4 bq = *reinterpret_cast<const float4*>(wh + d);
        float4 s = *reinterpret_cast<const float4*>(&sq[d]);
        acc += (a.x + bq.x) * s.x + (a.y + bq.y) * s.y + (a.z + bq.z) * s.z + (a.w + bq.w) * s.w;
    }
    c[k * 1024 + j] = acc;
}

// ---------------- attention (fused gather + optional fused LSTM) ----------------
template <int PASS>
__global__ void attn_kernel(const float* __restrict__ h4, const int* __restrict__ pn,
                            const float* __restrict__ gates, const float* __restrict__ bih,
                            const float* __restrict__ bhh, float* __restrict__ rout,
                            float* __restrict__ q1out) {
    int p = blockIdx.x, k = blockIdx.y;
    extern __shared__ float smdyn[];
    float* sx = smdyn;
    float* sq = smdyn + 64 * 256;
    float* dots = sq + 256;
    int* spn = (int*)(dots + 64);
    int tid = threadIdx.x;

    {
        const float* bi = bih + k * 1024;
        const float* bh = bhh + k * 1024;
        float bgi = bi[tid] + bh[tid];
        float bgg = bi[512 + tid] + bh[512 + tid];
        float bgo = bi[768 + tid] + bh[768 + tid];
        float cs0 = sigm(bgi) * tanhf(bgg);
        if (PASS == 0) {
            sq[tid] = sigm(bgo) * tanhf(cs0);
        } else {
            const float* g = gates + ((size_t)(k * P_PATH + p)) * 1024;
            float gi = g[tid], gf = g[256 + tid], gg = g[512 + tid], go = g[768 + tid];
            float cs = sigm(gf) * cs0 + sigm(gi) * tanhf(gg);
            float q = sigm(go) * tanhf(cs);
            sq[tid] = q;
            q1out[((size_t)k * P_PATH + p) * 256 + tid] = q;
        }
    }
    if (tid < 64) spn[tid] = pn[p * 64 + tid];
    __syncthreads();

    const float4* h4v = reinterpret_cast<const float4*>(h4);
    float4* sxv = reinterpret_cast<float4*>(sx);
    for (int i = tid; i < 64 * 64; i += 256) {
        int s = i >> 6, c = i & 63;
        sxv[i] = h4v[(size_t)spn[s] * 64 + c];
    }
    __syncthreads();

    int w = tid >> 5, lane = tid & 31;
    for (int s = w; s < 64; s += 8) {
        const float* xr = sx + s * 256;
        float part = 0.f;
#pragma unroll
        for (int m = 0; m < 8; m++) part += xr[lane + 32 * m] * sq[lane + 32 * m];
        for (int off = 16; off; off >>= 1) part += __shfl_down_sync(0xffffffffu, part, off);
        if (lane == 0) dots[s] = part;
    }
    __syncthreads();
    if (w == 0) {
        float a = dots[lane], b = dots[lane + 32];
        float mx = fmaxf(a, b);
        for (int off = 16; off; off >>= 1) mx = fmaxf(mx, __shfl_xor_sync(0xffffffffu, mx, off));
        float e0 = __expf(a - mx), e1 = __expf(b - mx);
        float sum = e0 + e1;
        for (int off = 16; off; off >>= 1) sum += __shfl_xor_sync(0xffffffffu, sum, off);
        float inv = 1.f / sum;
        dots[lane] = e0 * inv;
        dots[lane + 32] = e1 * inv;
    }
    __syncthreads();
    float acc = 0.f;
#pragma unroll 8
    for (int s = 0; s < 64; s++) acc += dots[s] * sx[s * 256 + tid];
    rout[((size_t)k * P_PATH + p) * 256 + tid] = acc;
}

// ---------------- gates1 = c[k,:] + r0 @ Wih[:, D:2D]^T  (f32x2, 32-row tiles) ----------------
__global__ void gates_gemm(const float* __restrict__ r0, const float* __restrict__ Wih,
                           const float* __restrict__ c, float* __restrict__ gates) {
    constexpr int RT = 32;
    int ct = blockIdx.x, rt = blockIdx.y, k = blockIdx.z;
    __shared__ __align__(16) float sR[RT * 256];
    int tid = threadIdx.x;
    const float* rbase = r0 + ((size_t)k * P_PATH + rt * RT) * 256;
    for (int i = tid; i < RT * 256; i += 256) sR[i] = rbase[i];
    __syncthreads();
    int j = ct * 256 + tid;
    const ull* wrow = reinterpret_cast<const ull*>(Wih + ((size_t)k * 1024 + j) * 512 + 256);
    ull acc2[RT];
#pragma unroll
    for (int r = 0; r < RT; r++) acc2[r] = 0ull;
    for (int d = 0; d < 256; d += 4) {
        ull w01 = wrow[d / 2];
        ull w23 = wrow[d / 2 + 1];
#pragma unroll
        for (int r = 0; r < RT; r++) {
            const ull* sp = reinterpret_cast<const ull*>(&sR[r * 256]);
            ffma2(acc2[r], w01, sp[d / 2]);
            ffma2(acc2[r], w23, sp[d / 2 + 1]);
        }
    }
    float cj = c[k * 1024 + j];
#pragma unroll
    for (int r = 0; r < RT; r++)
        gates[((size_t)k * P_PATH + rt * RT + r) * 1024 + j] = hsum2(acc2[r]) + cj;
}

// ---------------- xg[p] = bg + sum_k (q1_k . Wg_q + r1_k . Wg_r) ----------------
__global__ void xg_kernel(const float* __restrict__ q1, const float* __restrict__ r1,
                          const float* __restrict__ Wg, const float* __restrict__ bg,
                          float* __restrict__ xg) {
    int p = blockIdx.x, tid = threadIdx.x;
    float acc = 0.f;
#pragma unroll
    for (int k = 0; k < 3; k++) {
        acc += q1[((size_t)k * P_PATH + p) * 256 + tid] * Wg[k * 512 + tid];
        acc += r1[((size_t)k * P_PATH + p) * 256 + tid] * Wg[k * 512 + 256 + tid];
    }
    __shared__ float sred[8];
    for (int off = 16; off; off >>= 1) acc += __shfl_xor_sync(0xffffffffu, acc, off);
    if ((tid & 31) == 0) sred[tid >> 5] = acc;
    __syncthreads();
    if (tid == 0) {
        float t = 0.f;
#pragma unroll
        for (int i = 0; i < 8; i++) t += sred[i];
        xg[p] = t + bg[0];
    }
}

// ---------------- final MLP ----------------
__global__ void final_kernel(const float* __restrict__ xg, const float* __restrict__ Wl1,
                             const float* __restrict__ bl1, const float* __restrict__ Wl2,
                             const float* __restrict__ bl2, const float* __restrict__ Wl3,
                             const float* __restrict__ bl3, float* __restrict__ out) {
    __shared__ __align__(16) float sxg[512];
    __shared__ __align__(16) float sz1[256];
    __shared__ float sz2[64];
    int tid = threadIdx.x;
    sxg[tid] = xg[tid];
    sxg[tid + 256] = xg[tid + 256];
    __syncthreads();
    {
        float a = bl1[tid];
        const float* w = Wl1 + (size_t)tid * 512;
        for (int p = 0; p < 512; p += 4) {
            float4 w4 = *reinterpret_cast<const float4*>(w + p);
            float4 x4 = *reinterpret_cast<const float4*>(&sxg[p]);
            a += w4.x * x4.x + w4.y * x4.y + w4.z * x4.z + w4.w * x4.w;
        }
        sz1[tid] = tanhf(a);
    }
    __syncthreads();
    if (tid < 64) {
        float bacc = bl2[tid];
        const float* w2 = Wl2 + (size_t)tid * 256;
        for (int hh = 0; hh < 256; hh += 4) {
            float4 w4 = *reinterpret_cast<const float4*>(w2 + hh);
            float4 z4 = *reinterpret_cast<const float4*>(&sz1[hh]);
            bacc += w4.x * z4.x + w4.y * z4.y + w4.z * z4.z + w4.w * z4.w;
        }
        sz2[tid] = fmaxf(bacc, 0.f);
    }
    __syncthreads();
    if (tid == 0) {
        float cacc = bl3[0];
        for (int j = 0; j < 64; j++) cacc += sz2[j] * Wl3[j];
        out[0] = 1.f / (1.f + __expf(-cacc));
    }
}

// ---------------- host launcher ----------------
extern "C" void kernel_launch(void* const* d_in, const int* in_sizes, int n_in,
                              void* d_out, int out_size) {
    const float* h = (const float*)d_in[0];
    const int* src = (const int*)d_in[1];
    const int* dst = (const int*)d_in[2];
    const int* pn = (const int*)d_in[3];
    const float* W1 = (const float*)d_in[4];
    const float* b1 = (const float*)d_in[5];
    const float* W2 = (const float*)d_in[6];
    const float* b2 = (const float*)d_in[7];
    const float* W3 = (const float*)d_in[8];
    const float* b3 = (const float*)d_in[9];
    const float* W4 = (const float*)d_in[10];
    const float* b4 = (const float*)d_in[11];
    const float* Wih = (const float*)d_in[12];
    const float* Whh = (const float*)d_in[13];
    const float* bih = (const float*)d_in[14];
    const float* bhh = (const float*)d_in[15];
    const float* Wg = (const float*)d_in[16];
    const float* bg = (const float*)d_in[17];
    const float* Wl1 = (const float*)d_in[18];
    const float* bl1 = (const float*)d_in[19];
    const float* Wl2 = (const float*)d_in[20];
    const float* bl2 = (const float*)d_in[21];
    const float* Wl3 = (const float*)d_in[22];
    const float* bl3 = (const float*)d_in[23];
    int E = in_sizes[1];
    float* out = (float*)d_out;

    float *agg, *part, *h1, *h2, *h3, *h4, *cvec, *r0, *gates, *q1, *r1, *xg;
    int *deg, *off, *cur, *srcs;
    cudaGetSymbolAddress((void**)&agg, g_agg);
    cudaGetSymbolAddress((void**)&part, g_part);
    cudaGetSymbolAddress((void**)&h1, g_h1);
    cudaGetSymbolAddress((void**)&h2, g_h2);
    cudaGetSymbolAddress((void**)&h3, g_h3);
    cudaGetSymbolAddress((void**)&h4, g_h4);
    cudaGetSymbolAddress((void**)&cvec, g_c);
    cudaGetSymbolAddress((void**)&r0, g_r0);
    cudaGetSymbolAddress((void**)&gates, g_gates);
    cudaGetSymbolAddress((void**)&q1, g_q1);
    cudaGetSymbolAddress((void**)&r1, g_r1);
    cudaGetSymbolAddress((void**)&xg, g_xg);
    cudaGetSymbolAddress((void**)&deg, g_deg);
    cudaGetSymbolAddress((void**)&off, g_off);
    cudaGetSymbolAddress((void**)&cur, g_cur);
    cudaGetSymbolAddress((void**)&srcs, g_srcs);

    // GEMM smem: (N*(K+4) + RPB*K) * 4 bytes
    const int smem1 = (24 * 12 + 32 * 8) * 4;
    const int smem2 = (64 * 28 + 32 * 24) * 4;
    const int smem3 = (128 * 68 + 64 * 64) * 4;
    const int smem4 = (256 * 132 + 64 * 128) * 4;  // ~168 KB
    cudaFuncSetAttribute(gemm_relu<64, 128, 128, 512, 64, 0>,
                         cudaFuncAttributeMaxDynamicSharedMemorySize, smem3);
    cudaFuncSetAttribute(gemm_relu<128, 256, 256, 512, 64, 0>,
                         cudaFuncAttributeMaxDynamicSharedMemorySize, smem4);
    const int attn_smem = (64 * 256 + 256 + 64 + 64) * 4;
    cudaFuncSetAttribute(attn_kernel<0>, cudaFuncAttributeMaxDynamicSharedMemorySize, attn_smem);
    cudaFuncSetAttribute(attn_kernel<1>, cudaFuncAttributeMaxDynamicSharedMemorySize, attn_smem);

    // agg_tma smem: 2*BATCH*ROWB + 16 (mbars) + 2048 (combine)
    const int tsm24 = 2 * 64 * 96 + 16 + 2048;    // 14.4 KB
    const int tsm64 = 2 * 64 * 256 + 16 + 2048;   // 34.8 KB
    const int tsm128 = 2 * 32 * 512 + 16 + 2048;  // 34.8 KB

    // ---- CSR build ----
    cudaMemsetAsync(deg, 0, NN * sizeof(int));
    hist_kernel<<<(E + 255) / 256, 256>>>(dst, deg, E);
    scan_kernel<<<1, 1024>>>(deg, off, cur);
    bucket_kernel<<<(E + 255) / 256, 256>>>(src, dst, cur, srcs, E);

    // ---- 4 GIN layers ----
    // layer 1: D=8, LDG sliced (rows too small for TMA)
    aggregate_sliced<8, 8><<<(NN * 2 * 8 + 255) / 256, 256>>>(h, off, srcs, part);
    gemm_relu<8, 24, 32, 256, 32, 8><<<(NN + 31) / 32, 256, smem1>>>(h, part, W1, b1, h1, NN);

    // layer 2: D=24, TMA gather (96B rows)
    agg_tma<24, 64, 4><<<NN / 4, 128, tsm24>>>(h1, off, srcs, agg);
    gemm_relu<24, 64, 64, 256, 32, 0><<<(NN + 31) / 32, 256, smem2>>>(agg, nullptr, W2, b2, h2,
                                                                      NN);

    // layer 3: D=64, TMA gather (256B rows)
    agg_tma<64, 64, 4><<<NN / 4, 128, tsm64>>>(h2, off, srcs, agg);
    gemm_relu<64, 128, 128, 512, 64, 0><<<(NN + 63) / 64, 512, smem3>>>(agg, nullptr, W3, b3,
                                                                        h3, NN);

    // layer 4: D=128, TMA gather (512B rows)
    agg_tma<128, 32, 4><<<NN / 4, 128, tsm128>>>(h3, off, srcs, agg);
    gemm_relu<128, 256, 256, 512, 64, 0><<<(NN + 63) / 64, 512, smem4>>>(agg, nullptr, W4, b4,
                                                                         h4, NN);

    // ---- Set2Set (3 modules batched via grid.y) ----
    attn_kernel<0><<<dim3(P_PATH, 3), 256, attn_smem>>>(h4, pn, nullptr, bih, bhh, r0, nullptr);
    s2s_cvec<<<dim3(4, 3), 256>>>(Wih, Whh, bih, bhh, cvec);
    gates_gemm<<<dim3(4, P_PATH / 32, 3), 256>>>(r0, Wih, cvec, gates);
    attn_kernel<1><<<dim3(P_PATH, 3), 256, attn_smem>>>(h4, pn, gates, bih, bhh, r1, q1);

    xg_kernel<<<P_PATH, 256>>>(q1, r1, Wg, bg, xg);
    final_kernel<<<1, 256>>>(xg, Wl1, bl1, Wl2, bl2, Wl3, bl3, out);
}

// round 6
// speedup vs baseline: 1.3294x; 1.3294x over previous
#include <cuda_runtime.h>
#include <cuda_bf16.h>
#include <cstdint>

#define NN 20000
#define NE 640000
#define P_PATH 512
#define S_SUB 64
#define DHID 256

// ---------------- scratch (static device globals; no allocation) ----------------
static __device__ __align__(16) float g_agg[NN * 128];
static __device__ __align__(16) float g_part[NN * 256];
static __device__ __align__(16) float g_h1[NN * 24];
static __device__ __align__(16) float g_h2[NN * 64];
static __device__ __align__(16) float g_h3[NN * 128];
static __device__ __align__(16) float g_h4[NN * 256];
static __device__ int g_deg[NN];
static __device__ int g_off[NN + 1];
static __device__ int g_cur[NN];
static __device__ int g_srcs[NE];
static __device__ float g_q0[3 * 256];
static __device__ float g_cs0[3 * 256];
static __device__ float g_c[3 * 1024];
static __device__ __align__(16) float g_r0[3 * P_PATH * 256];
static __device__ __align__(16) float g_gates[3 * P_PATH * 1024];
static __device__ __align__(16) float g_q1[3 * P_PATH * 256];
static __device__ __align__(16) float g_r1[3 * P_PATH * 256];
static __device__ float g_xg[P_PATH];

__device__ __forceinline__ float sigm(float x) { return 1.f / (1.f + __expf(-x)); }

#define CPA_COMMIT() asm volatile("cp.async.commit_group;" ::: "memory")
#define CPA_WAIT(n) asm volatile("cp.async.wait_group %0;" ::"n"(n) : "memory")

// ---------------- CSR build ----------------
__global__ void hist_kernel(const int* __restrict__ dst, int* __restrict__ deg, int E) {
    int e = blockIdx.x * blockDim.x + threadIdx.x;
    if (e < E) atomicAdd(&deg[dst[e]], 1);
}

__global__ void scan_kernel(const int* __restrict__ deg, int* __restrict__ off,
                            int* __restrict__ cur) {
    __shared__ int part[1024];
    int t = threadIdx.x;
    const int CH = (NN + 1023) / 1024;
    int start = t * CH;
    int end = min(start + CH, NN);
    int s = 0;
    for (int i = start; i < end; i++) s += deg[i];
    part[t] = s;
    __syncthreads();
    for (int o = 1; o < 1024; o <<= 1) {
        int v = (t >= o) ? part[t - o] : 0;
        __syncthreads();
        part[t] += v;
        __syncthreads();
    }
    int base = (t > 0) ? part[t - 1] : 0;
    for (int i = start; i < end; i++) {
        off[i] = base;
        cur[i] = base;
        base += deg[i];
    }
    if (t == 1023) off[NN] = part[1023];
}

__global__ void bucket_kernel(const int* __restrict__ src, const int* __restrict__ dst,
                              int* __restrict__ cur, int* __restrict__ srcs, int E) {
    int e = blockIdx.x * blockDim.x + threadIdx.x;
    if (e < E) {
        int p = atomicAdd(&cur[dst[e]], 1);
        srcs[p] = src[e];
    }
}

// ---------------- sliced aggregation (small D): NS partial sums per node ----------------
template <int D, int NS>
__global__ void aggregate_sliced(const float* __restrict__ h, const int* __restrict__ off,
                                 const int* __restrict__ srcs, float* __restrict__ part) {
    constexpr int C = D / 4;
    int idx = blockIdx.x * blockDim.x + threadIdx.x;
    if (idx >= NN * C * NS) return;
    int slice = idx / (NN * C);
    int rem = idx - slice * NN * C;
    int node = rem / C;
    int c = rem - node * C;
    const float4* hp = reinterpret_cast<const float4*>(h);
    int s0 = off[node], s1 = off[node + 1];
    int len = s1 - s0;
    int a = s0 + (len * slice) / NS;
    int b = s0 + (len * (slice + 1)) / NS;
    float4 acc = {0.f, 0.f, 0.f, 0.f};
#pragma unroll 4
    for (int j = a; j < b; j++) {
        int s = __ldg(&srcs[j]);
        float4 v = hp[(size_t)s * C + c];
        acc.x += v.x;
        acc.y += v.y;
        acc.z += v.z;
        acc.w += v.w;
    }
    reinterpret_cast<float4*>(part)[idx] = acc;
}

template <int D, int NS>
__global__ void combine_k(const float* __restrict__ h, const float* __restrict__ part,
                          float* __restrict__ outp) {
    constexpr int C = D / 4;
    int idx = blockIdx.x * blockDim.x + threadIdx.x;
    if (idx >= NN * C) return;
    const float4* hp = reinterpret_cast<const float4*>(h);
    const float4* pp = reinterpret_cast<const float4*>(part);
    float4 acc = hp[idx];
#pragma unroll
    for (int s = 0; s < NS; s++) {
        float4 v = pp[(size_t)s * NN * C + idx];
        acc.x += v.x;
        acc.y += v.y;
        acc.z += v.z;
        acc.w += v.w;
    }
    reinterpret_cast<float4*>(outp)[idx] = acc;
}

// ---------------- cp.async pipelined gather aggregation (D = 64 or 128) ----------------
// One warp per node. srcs staged in smem; neighbor rows copied via LDGSTS in a
// 3-deep group pipeline; each lane accumulates exactly the bytes it copied.
template <int D>
__global__ void agg_cpasync(const float* __restrict__ h, const int* __restrict__ off,
                            const int* __restrict__ srcs, float* __restrict__ outp) {
    constexpr int ROWB = D * 4;      // 256 or 512 bytes per row
    constexpr int LPR = ROWB / 16;   // lanes per row: 16 or 32
    constexpr int RPI = 32 / LPR;    // rows per issue round: 2 or 1
    constexpr int GROUP = 8;         // rows (edges) per pipeline group
    constexpr int NBUF = 3;
    constexpr int WARPS = (D == 128) ? 4 : 8;
    constexpr int CAP = 128;  // staged srcs per node
    constexpr int WBYTES = NBUF * GROUP * ROWB;
    extern __shared__ __align__(16) char smraw[];

    int wid = threadIdx.x >> 5, lane = threadIdx.x & 31;
    int node = blockIdx.x * WARPS + wid;
    if (node >= NN) return;

    char* wbase = smraw + (size_t)wid * WBYTES;
    int* s_sm = (int*)(smraw + (size_t)WARPS * WBYTES) + wid * CAP;
    uint32_t wu32;
    asm("{ .reg .u64 t; cvta.to.shared.u64 t, %1; cvt.u32.u64 %0, t; }"
        : "=r"(wu32)
        : "l"(wbase));

    int s0 = off[node];
    int len = off[node + 1] - s0;
    int staged = min(len, CAP);
    for (int i = lane; i < staged; i += 32) s_sm[i] = srcs[s0 + i];
    __syncwarp();

    int ngroups = (len + GROUP - 1) / GROUP;
    int sub = lane / LPR;   // row-within-round (0..RPI-1)
    int cl = lane % LPR;    // 16B chunk within row

    // ---- issue a group g (rows g*GROUP .. min(+GROUP,len)-1) ----
    auto issue = [&](int g) {
        uint32_t slot = wu32 + (uint32_t)((g % NBUF) * GROUP) * ROWB;
#pragma unroll
        for (int ri = 0; ri < GROUP / RPI; ri++) {
            int rr = ri * RPI + sub;    // row index within group
            int r = g * GROUP + rr;     // edge index within node
            if (r < len) {
                int s = (r < staged) ? s_sm[r] : __ldg(&srcs[s0 + r]);
                const char* gp = (const char*)(h + (size_t)s * D) + cl * 16;
                uint32_t sp = slot + (uint32_t)rr * ROWB + cl * 16;
                asm volatile("cp.async.cg.shared.global [%0], [%1], 16;" ::"r"(sp), "l"(gp)
                             : "memory");
            }
        }
    };

    // prologue: NBUF committed groups (empty ones keep the count exact)
    for (int g = 0; g < NBUF; g++) {
        if (g < ngroups) issue(g);
        CPA_COMMIT();
    }

    float4 acc = {0.f, 0.f, 0.f, 0.f};
    for (int g = 0; g < ngroups; g++) {
        CPA_WAIT(NBUF - 1);  // group g complete
        __syncwarp();
        int cnt = min(GROUP, len - g * GROUP);
        const char* slot = wbase + (size_t)((g % NBUF) * GROUP) * ROWB;
        for (int r = sub; r < cnt; r += RPI) {
            float4 v = *reinterpret_cast<const float4*>(slot + (size_t)r * ROWB + cl * 16);
            acc.x += v.x;
            acc.y += v.y;
            acc.z += v.z;
            acc.w += v.w;
        }
        int gn = g + NBUF;
        if (gn < ngroups) issue(gn);
        CPA_COMMIT();
    }
    CPA_WAIT(0);

    const float4* h4 = reinterpret_cast<const float4*>(h);
    float4* o4 = reinterpret_cast<float4*>(outp);
    if (RPI == 2) {  // D=64: fold the two row-parity halves
        acc.x += __shfl_down_sync(0xffffffffu, acc.x, 16);
        acc.y += __shfl_down_sync(0xffffffffu, acc.y, 16);
        acc.z += __shfl_down_sync(0xffffffffu, acc.z, 16);
        acc.w += __shfl_down_sync(0xffffffffu, acc.w, 16);
        if (lane < LPR) {
            float4 b = h4[(size_t)node * LPR + lane];
            b.x += acc.x;
            b.y += acc.y;
            b.z += acc.z;
            b.w += acc.w;
            o4[(size_t)node * LPR + lane] = b;
        }
    } else {  // D=128
        float4 b = h4[(size_t)node * 32 + lane];
        b.x += acc.x;
        b.y += acc.y;
        b.z += acc.z;
        b.w += acc.w;
        o4[(size_t)node * 32 + lane] = b;
    }
}

// ---------------- GIN GEMM: out = relu(xin @ W^T + b) ----------------
template <int K, int N, int NP, int T, int RPB>
__global__ void gemm_relu(const float* __restrict__ xin, const float* __restrict__ W,
                          const float* __restrict__ b, float* __restrict__ out, int nrows) {
    constexpr int LDK = K + 4;
    constexpr int G = T / NP;
    constexpr int RPT = RPB / G;
    extern __shared__ float sm[];
    float* sW = sm;            // N * LDK
    float* sR = sm + N * LDK;  // RPB * K
    int tid = threadIdx.x;
    for (int i = tid; i < K * N; i += T) {
        int j = i / K, k = i - j * K;
        sW[j * LDK + k] = W[i];
    }
    int row0 = blockIdx.x * RPB;
    for (int i = tid; i < RPB * K; i += T) {
        int r = i / K, k = i - r * K;
        int row = row0 + r;
        sR[i] = (row < nrows) ? xin[(size_t)row * K + k] : 0.f;
    }
    __syncthreads();
    int j = tid % NP;
    int rg = tid / NP;
    if (j < N) {
        float acc[RPT];
#pragma unroll
        for (int t = 0; t < RPT; t++) acc[t] = 0.f;
        for (int k = 0; k < K; k += 4) {
            float4 w4 = *reinterpret_cast<const float4*>(&sW[j * LDK + k]);
#pragma unroll
            for (int t = 0; t < RPT; t++) {
                float4 s4 = *reinterpret_cast<const float4*>(&sR[(rg + t * G) * K + k]);
                acc[t] += s4.x * w4.x + s4.y * w4.y + s4.z * w4.z + s4.w * w4.w;
            }
        }
        float bj = b[j];
#pragma unroll
        for (int t = 0; t < RPT; t++) {
            int row = row0 + rg + t * G;
            if (row < nrows) out[(size_t)row * N + j] = fmaxf(acc[t] + bj, 0.f);
        }
    }
}

// ---------------- Set2Set iter-0 constants ----------------
__global__ void s2s_init(const float* __restrict__ bih, const float* __restrict__ bhh,
                         float* __restrict__ cs0, float* __restrict__ q0) {
    int idx = blockIdx.x * blockDim.x + threadIdx.x;
    if (idx >= 3 * 256) return;
    int k = idx >> 8, d = idx & 255;
    const float* bi = bih + k * 1024;
    const float* bh = bhh + k * 1024;
    float gi = bi[d] + bh[d];
    float gg = bi[512 + d] + bh[512 + d];
    float go = bi[768 + d] + bh[768 + d];
    float cs = sigm(gi) * tanhf(gg);
    cs0[idx] = cs;
    q0[idx] = sigm(go) * tanhf(cs);
}

// c[k,j] = bih+bhh + sum_d q0[k,d]*(Wih[k,j,d] + Whh[k,j,d])
__global__ void s2s_cvec(const float* __restrict__ Wih, const float* __restrict__ Whh,
                         const float* __restrict__ bih, const float* __restrict__ bhh,
                         const float* __restrict__ q0, float* __restrict__ c) {
    int k = blockIdx.y;
    int j = blockIdx.x * 256 + threadIdx.x;
    __shared__ __align__(16) float sq[256];
    sq[threadIdx.x] = q0[k * 256 + threadIdx.x];
    __syncthreads();
    const float* wi = Wih + ((size_t)k * 1024 + j) * 512;
    const float* wh = Whh + ((size_t)k * 1024 + j) * 256;
    float acc = bih[k * 1024 + j] + bhh[k * 1024 + j];
    for (int d = 0; d < 256; d += 4) {
        float4 a = *reinterpret_cast<const float4*>(wi + d);
        float4 bq = *reinterpret_cast<const float4*>(wh + d);
        float4 s = *reinterpret_cast<const float4*>(&sq[d]);
        acc += (a.x + bq.x) * s.x + (a.y + bq.y) * s.y + (a.z + bq.z) * s.z + (a.w + bq.w) * s.w;
    }
    c[k * 1024 + j] = acc;
}

// ---------------- attention (fused gather): x tile staged in smem ----------------
__global__ void attn_kernel(const float* __restrict__ h4, const int* __restrict__ pn,
                            const float* __restrict__ query, int perP,
                            float* __restrict__ rout) {
    int p = blockIdx.x, k = blockIdx.y;
    extern __shared__ float smdyn[];
    float* sx = smdyn;
    float* sq = smdyn + 64 * 256;
    float* dots = sq + 256;
    int* spn = (int*)(dots + 64);
    int tid = threadIdx.x;

    const float* q = query + (perP ? ((size_t)(k * P_PATH + p) * 256) : ((size_t)k * 256));
    sq[tid] = q[tid];
    if (tid < 64) spn[tid] = pn[p * 64 + tid];
    __syncthreads();

    const float4* h4v = reinterpret_cast<const float4*>(h4);
    float4* sxv = reinterpret_cast<float4*>(sx);
    for (int i = tid; i < 64 * 64; i += 256) {
        int s = i >> 6, c = i & 63;
        sxv[i] = h4v[(size_t)spn[s] * 64 + c];
    }
    __syncthreads();

    int w = tid >> 5, lane = tid & 31;
    for (int s = w; s < 64; s += 8) {
        const float* xr = sx + s * 256;
        float part = 0.f;
#pragma unroll
        for (int m = 0; m < 8; m++) part += xr[lane + 32 * m] * sq[lane + 32 * m];
        for (int off = 16; off; off >>= 1) part += __shfl_down_sync(0xffffffffu, part, off);
        if (lane == 0) dots[s] = part;
    }
    __syncthreads();
    if (w == 0) {
        float a = dots[lane], b = dots[lane + 32];
        float mx = fmaxf(a, b);
        for (int off = 16; off; off >>= 1) mx = fmaxf(mx, __shfl_xor_sync(0xffffffffu, mx, off));
        float e0 = __expf(a - mx), e1 = __expf(b - mx);
        float sum = e0 + e1;
        for (int off = 16; off; off >>= 1) sum += __shfl_xor_sync(0xffffffffu, sum, off);
        float inv = 1.f / sum;
        dots[lane] = e0 * inv;
        dots[lane + 32] = e1 * inv;
    }
    __syncthreads();
    float acc = 0.f;
#pragma unroll 8
    for (int s = 0; s < 64; s++) acc += dots[s] * sx[s * 256 + tid];
    rout[((size_t)k * P_PATH + p) * 256 + tid] = acc;
}

// ---------------- gates1 = c[k,:] + r0 @ Wih[:, D:2D]^T   (32-row tiles) ----------------
__global__ void gates_gemm(const float* __restrict__ r0, const float* __restrict__ Wih,
                           const float* __restrict__ c, float* __restrict__ gates) {
    constexpr int RT = 32;
    int ct = blockIdx.x, rt = blockIdx.y, k = blockIdx.z;
    __shared__ __align__(16) float sR[RT * 256];
    int tid = threadIdx.x;
    const float* rbase = r0 + ((size_t)k * P_PATH + rt * RT) * 256;
    for (int i = tid; i < RT * 256; i += 256) sR[i] = rbase[i];
    __syncthreads();
    int j = ct * 256 + tid;
    const float* wrow = Wih + ((size_t)k * 1024 + j) * 512 + 256;
    float acc[RT];
#pragma unroll
    for (int r = 0; r < RT; r++) acc[r] = 0.f;
    for (int d = 0; d < 256; d += 4) {
        float4 w4 = *reinterpret_cast<const float4*>(wrow + d);
#pragma unroll
        for (int r = 0; r < RT; r++) {
            float4 s4 = *reinterpret_cast<const float4*>(&sR[r * 256 + d]);
            acc[r] += s4.x * w4.x + s4.y * w4.y + s4.z * w4.z + s4.w * w4.w;
        }
    }
    float cj = c[k * 1024 + j];
#pragma unroll
    for (int r = 0; r < RT; r++)
        gates[((size_t)k * P_PATH + rt * RT + r) * 1024 + j] = acc[r] + cj;
}

// ---------------- iter-1 LSTM elementwise -> q1 ----------------
__global__ void lstm_kernel(const float* __restrict__ gates, const float* __restrict__ cs0,
                            float* __restrict__ q1) {
    int idx = blockIdx.x * blockDim.x + threadIdx.x;
    if (idx >= 3 * P_PATH * 256) return;
    int d = idx & 255;
    int pk = idx >> 8;
    int k = pk >> 9;
    const float* g = gates + (size_t)pk * 1024;
    float gi = g[d], gf = g[256 + d], gg = g[512 + d], go = g[768 + d];
    float cs = sigm(gf) * cs0[k * 256 + d] + sigm(gi) * tanhf(gg);
    q1[idx] = sigm(go) * tanhf(cs);
}

// ---------------- xg ----------------
__global__ void xg_kernel(const float* __restrict__ q1, const float* __restrict__ r1,
                          const float* __restrict__ Wg, const float* __restrict__ bg,
                          float* __restrict__ xg) {
    int p = blockIdx.x, tid = threadIdx.x;
    float acc = 0.f;
#pragma unroll
    for (int k = 0; k < 3; k++) {
        acc += q1[((size_t)k * P_PATH + p) * 256 + tid] * Wg[k * 512 + tid];
        acc += r1[((size_t)k * P_PATH + p) * 256 + tid] * Wg[k * 512 + 256 + tid];
    }
    __shared__ float sred[8];
    for (int off = 16; off; off >>= 1) acc += __shfl_xor_sync(0xffffffffu, acc, off);
    if ((tid & 31) == 0) sred[tid >> 5] = acc;
    __syncthreads();
    if (tid == 0) {
        float t = 0.f;
#pragma unroll
        for (int i = 0; i < 8; i++) t += sred[i];
        xg[p] = t + bg[0];
    }
}

// ---------------- final MLP ----------------
__global__ void final_kernel(const float* __restrict__ xg, const float* __restrict__ Wl1,
                             const float* __restrict__ bl1, const float* __restrict__ Wl2,
                             const float* __restrict__ bl2, const float* __restrict__ Wl3,
                             const float* __restrict__ bl3, float* __restrict__ out) {
    __shared__ __align__(16) float sxg[512];
    __shared__ __align__(16) float sz1[256];
    __shared__ float sz2[64];
    int tid = threadIdx.x;
    sxg[tid] = xg[tid];
    sxg[tid + 256] = xg[tid + 256];
    __syncthreads();
    {
        float a = bl1[tid];
        const float* w = Wl1 + (size_t)tid * 512;
        for (int p = 0; p < 512; p += 4) {
            float4 w4 = *reinterpret_cast<const float4*>(w + p);
            float4 x4 = *reinterpret_cast<const float4*>(&sxg[p]);
            a += w4.x * x4.x + w4.y * x4.y + w4.z * x4.z + w4.w * x4.w;
        }
        sz1[tid] = tanhf(a);
    }
    __syncthreads();
    if (tid < 64) {
        float bacc = bl2[tid];
        const float* w2 = Wl2 + (size_t)tid * 256;
        for (int hh = 0; hh < 256; hh += 4) {
            float4 w4 = *reinterpret_cast<const float4*>(w2 + hh);
            float4 z4 = *reinterpret_cast<const float4*>(&sz1[hh]);
            bacc += w4.x * z4.x + w4.y * z4.y + w4.z * z4.z + w4.w * z4.w;
        }
        sz2[tid] = fmaxf(bacc, 0.f);
    }
    __syncthreads();
    if (tid == 0) {
        float cacc = bl3[0];
        for (int j = 0; j < 64; j++) cacc += sz2[j] * Wl3[j];
        out[0] = 1.f / (1.f + __expf(-cacc));
    }
}

// ---------------- host launcher ----------------
extern "C" void kernel_launch(void* const* d_in, const int* in_sizes, int n_in,
                              void* d_out, int out_size) {
    const float* h = (const float*)d_in[0];
    const int* src = (const int*)d_in[1];
    const int* dst = (const int*)d_in[2];
    const int* pn = (const int*)d_in[3];
    const float* W1 = (const float*)d_in[4];
    const float* b1 = (const float*)d_in[5];
    const float* W2 = (const float*)d_in[6];
    const float* b2 = (const float*)d_in[7];
    const float* W3 = (const float*)d_in[8];
    const float* b3 = (const float*)d_in[9];
    const float* W4 = (const float*)d_in[10];
    const float* b4 = (const float*)d_in[11];
    const float* Wih = (const float*)d_in[12];
    const float* Whh = (const float*)d_in[13];
    const float* bih = (const float*)d_in[14];
    const float* bhh = (const float*)d_in[15];
    const float* Wg = (const float*)d_in[16];
    const float* bg = (const float*)d_in[17];
    const float* Wl1 = (const float*)d_in[18];
    const float* bl1 = (const float*)d_in[19];
    const float* Wl2 = (const float*)d_in[20];
    const float* bl2 = (const float*)d_in[21];
    const float* Wl3 = (const float*)d_in[22];
    const float* bl3 = (const float*)d_in[23];
    int E = in_sizes[1];
    float* out = (float*)d_out;

    float *agg, *part, *h1, *h2, *h3, *h4, *q0, *cs0, *cvec, *r0, *gates, *q1, *r1, *xg;
    int *deg, *off, *cur, *srcs;
    cudaGetSymbolAddress((void**)&agg, g_agg);
    cudaGetSymbolAddress((void**)&part, g_part);
    cudaGetSymbolAddress((void**)&h1, g_h1);
    cudaGetSymbolAddress((void**)&h2, g_h2);
    cudaGetSymbolAddress((void**)&h3, g_h3);
    cudaGetSymbolAddress((void**)&h4, g_h4);
    cudaGetSymbolAddress((void**)&q0, g_q0);
    cudaGetSymbolAddress((void**)&cs0, g_cs0);
    cudaGetSymbolAddress((void**)&cvec, g_c);
    cudaGetSymbolAddress((void**)&r0, g_r0);
    cudaGetSymbolAddress((void**)&gates, g_gates);
    cudaGetSymbolAddress((void**)&q1, g_q1);
    cudaGetSymbolAddress((void**)&r1, g_r1);
    cudaGetSymbolAddress((void**)&xg, g_xg);
    cudaGetSymbolAddress((void**)&deg, g_deg);
    cudaGetSymbolAddress((void**)&off, g_off);
    cudaGetSymbolAddress((void**)&cur, g_cur);
    cudaGetSymbolAddress((void**)&srcs, g_srcs);

    // GEMM smem: (N*(K+4) + RPB*K) * 4 bytes
    const int smem1 = (24 * 12 + 32 * 8) * 4;
    const int smem2 = (64 * 28 + 32 * 24) * 4;
    const int smem3 = (128 * 68 + 64 * 64) * 4;
    const int smem4 = (256 * 132 + 64 * 128) * 4;  // ~168 KB
    cudaFuncSetAttribute(gemm_relu<64, 128, 128, 512, 64>,
                         cudaFuncAttributeMaxDynamicSharedMemorySize, smem3);
    cudaFuncSetAttribute(gemm_relu<128, 256, 256, 512, 64>,
                         cudaFuncAttributeMaxDynamicSharedMemorySize, smem4);
    const int attn_smem = (64 * 256 + 256 + 64 + 64) * 4;
    cudaFuncSetAttribute(attn_kernel, cudaFuncAttributeMaxDynamicSharedMemorySize, attn_smem);

    // agg_cpasync smem: WARPS*(NBUF*GROUP*ROWB) + WARPS*CAP*4
    const int cpa64 = 8 * (3 * 8 * 256) + 8 * 128 * 4;   // 51.2 KB
    const int cpa128 = 4 * (3 * 8 * 512) + 4 * 128 * 4;  // 51.2 KB
    cudaFuncSetAttribute(agg_cpasync<64>, cudaFuncAttributeMaxDynamicSharedMemorySize, cpa64);
    cudaFuncSetAttribute(agg_cpasync<128>, cudaFuncAttributeMaxDynamicSharedMemorySize, cpa128);

    // ---- CSR build ----
    cudaMemsetAsync(deg, 0, NN * sizeof(int));
    hist_kernel<<<(E + 255) / 256, 256>>>(dst, deg, E);
    scan_kernel<<<1, 1024>>>(deg, off, cur);
    bucket_kernel<<<(E + 255) / 256, 256>>>(src, dst, cur, srcs, E);

    // ---- 4 GIN layers ----
    // layer 1: D=8 sliced (NS=8)
    aggregate_sliced<8, 8><<<(NN * 2 * 8 + 255) / 256, 256>>>(h, off, srcs, part);
    combine_k<8, 8><<<(NN * 2 + 255) / 256, 256>>>(h, part, agg);
    gemm_relu<8, 24, 32, 256, 32><<<(NN + 31) / 32, 256, smem1>>>(agg, W1, b1, h1, NN);

    // layer 2: D=24 sliced (NS=4)
    aggregate_sliced<24, 4><<<(NN * 6 * 4 + 255) / 256, 256>>>(h1, off, srcs, part);
    combine_k<24, 4><<<(NN * 6 + 255) / 256, 256>>>(h1, part, agg);
    gemm_relu<24, 64, 64, 256, 32><<<(NN + 31) / 32, 256, smem2>>>(agg, W2, b2, h2, NN);

    // layer 3: D=64 cp.async pipelined gather (8 warps/block -> 8 nodes/block)
    agg_cpasync<64><<<(NN + 7) / 8, 256, cpa64>>>(h2, off, srcs, agg);
    gemm_relu<64, 128, 128, 512, 64><<<(NN + 63) / 64, 512, smem3>>>(agg, W3, b3, h3, NN);

    // layer 4: D=128 cp.async pipelined gather (4 warps/block -> 4 nodes/block)
    agg_cpasync<128><<<(NN + 3) / 4, 128, cpa128>>>(h3, off, srcs, agg);
    gemm_relu<128, 256, 256, 512, 64><<<(NN + 63) / 64, 512, smem4>>>(agg, W4, b4, h4, NN);

    // ---- Set2Set (3 modules batched via grid.y) ----
    s2s_init<<<3, 256>>>(bih, bhh, cs0, q0);
    attn_kernel<<<dim3(P_PATH, 3), 256, attn_smem>>>(h4, pn, q0, 0, r0);
    s2s_cvec<<<dim3(4, 3), 256>>>(Wih, Whh, bih, bhh, q0, cvec);
    gates_gemm<<<dim3(4, P_PATH / 32, 3), 256>>>(r0, Wih, cvec, gates);
    lstm_kernel<<<(3 * P_PATH * 256 + 255) / 256, 256>>>(gates, cs0, q1);
    attn_kernel<<<dim3(P_PATH, 3), 256, attn_smem>>>(h4, pn, q1, 1, r1);

    xg_kernel<<<P_PATH, 256>>>(q1, r1, Wg, bg, xg);
    final_kernel<<<1, 256>>>(xg, Wl1, bl1, Wl2, bl2, Wl3, bl3, out);
}

// round 7
// speedup vs baseline: 1.5603x; 1.1737x over previous
#include <cuda_runtime.h>
#include <cuda_bf16.h>
#include <cstdint>

#define NN 20000
#define NE 640000
#define P_PATH 512
#define S_SUB 64
#define DHID 256

typedef unsigned long long ull;

// ---------------- scratch (static device globals; no allocation) ----------------
static __device__ __align__(16) float g_agg[NN * 128];
static __device__ __align__(16) float g_part[NN * 256];
static __device__ __align__(16) float g_h1[NN * 24];
static __device__ __align__(16) float g_h2[NN * 64];
static __device__ __align__(16) float g_h3[NN * 128];
static __device__ __align__(16) float g_h4[NN * 256];
static __device__ __align__(16) float g_w3t[64 * 128];    // W3^T [K=64][N=128]
static __device__ __align__(16) float g_w4t[128 * 256];   // W4^T [K=128][N=256]
static __device__ int g_deg[NN];
static __device__ int g_off[NN + 1];
static __device__ int g_cur[NN];
static __device__ int g_srcs[NE];
static __device__ float g_c[3 * 1024];
static __device__ __align__(16) float g_r0[3 * P_PATH * 256];
static __device__ __align__(16) float g_gates[3 * P_PATH * 1024];
static __device__ float g_xg[P_PATH];

__device__ __forceinline__ float sigm(float x) { return 1.f / (1.f + __expf(-x)); }

__device__ __forceinline__ void ffma2(ull& acc, ull a, ull b) {
    asm("fma.rn.f32x2 %0, %1, %2, %0;" : "+l"(acc) : "l"(a), "l"(b));
}
__device__ __forceinline__ float hsum2(ull v) {
    return __uint_as_float((unsigned)v) + __uint_as_float((unsigned)(v >> 32));
}

// ---------------- CSR build ----------------
__global__ void hist_kernel(const int* __restrict__ dst, int* __restrict__ deg, int E) {
    int e = blockIdx.x * blockDim.x + threadIdx.x;
    if (e < E) atomicAdd(&deg[dst[e]], 1);
}

__global__ void scan_kernel(const int* __restrict__ deg, int* __restrict__ off,
                            int* __restrict__ cur) {
    __shared__ int part[1024];
    int t = threadIdx.x;
    const int CH = (NN + 1023) / 1024;
    int start = t * CH;
    int end = min(start + CH, NN);
    int s = 0;
    for (int i = start; i < end; i++) s += deg[i];
    part[t] = s;
    __syncthreads();
    for (int o = 1; o < 1024; o <<= 1) {
        int v = (t >= o) ? part[t - o] : 0;
        __syncthreads();
        part[t] += v;
        __syncthreads();
    }
    int base = (t > 0) ? part[t - 1] : 0;
    for (int i = start; i < end; i++) {
        off[i] = base;
        cur[i] = base;
        base += deg[i];
    }
    if (t == 1023) off[NN] = part[1023];
}

__global__ void bucket_kernel(const int* __restrict__ src, const int* __restrict__ dst,
                              int* __restrict__ cur, int* __restrict__ srcs, int E) {
    int e = blockIdx.x * blockDim.x + threadIdx.x;
    if (e < E) {
        int p = atomicAdd(&cur[dst[e]], 1);
        srcs[p] = src[e];
    }
}

// ---------------- W transpose: WT[k][n] = W[n][k] ----------------
template <int K, int N>
__global__ void wtrans(const float* __restrict__ W, float* __restrict__ WT) {
    int i = blockIdx.x * 256 + threadIdx.x;
    if (i < K * N) {
        int n = i % N, k = i / N;
        WT[k * N + n] = W[n * K + k];
    }
}

// ---------------- direct gather aggregation (large D) ----------------
template <int D>
__global__ void aggregate_k(const float* __restrict__ h, const int* __restrict__ off,
                            const int* __restrict__ srcs, float* __restrict__ outp) {
    constexpr int C = D / 4;
    int idx = blockIdx.x * blockDim.x + threadIdx.x;
    if (idx >= NN * C) return;
    int node = idx / C;
    int c = idx - node * C;
    const float4* hp = reinterpret_cast<const float4*>(h);
    float4 acc = hp[(size_t)node * C + c];
    int s0 = off[node], s1 = off[node + 1];
#pragma unroll 8
    for (int j = s0; j < s1; j++) {
        int s = __ldg(&srcs[j]);
        float4 v = hp[(size_t)s * C + c];
        acc.x += v.x;
        acc.y += v.y;
        acc.z += v.z;
        acc.w += v.w;
    }
    reinterpret_cast<float4*>(outp)[idx] = acc;
}

// ---------------- sliced aggregation (small D) ----------------
template <int D, int NS>
__global__ void aggregate_sliced(const float* __restrict__ h, const int* __restrict__ off,
                                 const int* __restrict__ srcs, float* __restrict__ part) {
    constexpr int C = D / 4;
    int idx = blockIdx.x * blockDim.x + threadIdx.x;
    if (idx >= NN * C * NS) return;
    int slice = idx / (NN * C);
    int rem = idx - slice * NN * C;
    int node = rem / C;
    int c = rem - node * C;
    const float4* hp = reinterpret_cast<const float4*>(h);
    int s0 = off[node], s1 = off[node + 1];
    int len = s1 - s0;
    int a = s0 + (len * slice) / NS;
    int b = s0 + (len * (slice + 1)) / NS;
    float4 acc = {0.f, 0.f, 0.f, 0.f};
#pragma unroll 4
    for (int j = a; j < b; j++) {
        int s = __ldg(&srcs[j]);
        float4 v = hp[(size_t)s * C + c];
        acc.x += v.x;
        acc.y += v.y;
        acc.z += v.z;
        acc.w += v.w;
    }
    reinterpret_cast<float4*>(part)[idx] = acc;
}

template <int D, int NS>
__global__ void combine_k(const float* __restrict__ h, const float* __restrict__ part,
                          float* __restrict__ outp) {
    constexpr int C = D / 4;
    int idx = blockIdx.x * blockDim.x + threadIdx.x;
    if (idx >= NN * C) return;
    const float4* hp = reinterpret_cast<const float4*>(h);
    const float4* pp = reinterpret_cast<const float4*>(part);
    float4 acc = hp[idx];
#pragma unroll
    for (int s = 0; s < NS; s++) {
        float4 v = pp[(size_t)s * NN * C + idx];
        acc.x += v.x;
        acc.y += v.y;
        acc.z += v.z;
        acc.w += v.w;
    }
    reinterpret_cast<float4*>(outp)[idx] = acc;
}

// ---------------- small GIN GEMM (layers 1-2): out = relu(xin @ W^T + b) ----------------
template <int K, int N, int NP, int T, int RPB>
__global__ void gemm_relu(const float* __restrict__ xin, const float* __restrict__ W,
                          const float* __restrict__ b, float* __restrict__ out, int nrows) {
    constexpr int LDK = K + 4;
    constexpr int G = T / NP;
    constexpr int RPT = RPB / G;
    extern __shared__ float sm[];
    float* sW = sm;
    float* sR = sm + N * LDK;
    int tid = threadIdx.x;
    for (int i = tid; i < K * N; i += T) {
        int j = i / K, k = i - j * K;
        sW[j * LDK + k] = W[i];
    }
    int row0 = blockIdx.x * RPB;
    for (int i = tid; i < RPB * K; i += T) {
        int r = i / K, k = i - r * K;
        int row = row0 + r;
        sR[i] = (row < nrows) ? xin[(size_t)row * K + k] : 0.f;
    }
    __syncthreads();
    int j = tid % NP;
    int rg = tid / NP;
    if (j < N) {
        float acc[RPT];
#pragma unroll
        for (int t = 0; t < RPT; t++) acc[t] = 0.f;
        for (int k = 0; k < K; k += 4) {
            float4 w4 = *reinterpret_cast<const float4*>(&sW[j * LDK + k]);
#pragma unroll
            for (int t = 0; t < RPT; t++) {
                float4 s4 = *reinterpret_cast<const float4*>(&sR[(rg + t * G) * K + k]);
                acc[t] += s4.x * w4.x + s4.y * w4.y + s4.z * w4.z + s4.w * w4.w;
            }
        }
        float bj = b[j];
#pragma unroll
        for (int t = 0; t < RPT; t++) {
            int row = row0 + rg + t * G;
            if (row < nrows) out[(size_t)row * N + j] = fmaxf(acc[t] + bj, 0.f);
        }
    }
}

// ---------------- register-tiled GEMM (layers 3-4): out = relu(X @ W^T + b) ----------------
// X:[nrows][K], WT:[K][N] (pre-transposed). Tile 64m x 64n, 256 threads, thread = 4m x 4n.
template <int K, int N>
__global__ void gemm_rt(const float* __restrict__ X, const float* __restrict__ WT,
                        const float* __restrict__ b, float* __restrict__ out, int nrows) {
    constexpr int TM = 64, TN = 64;
    extern __shared__ float sm[];
    float* sA = sm;            // [TM][K]
    float* sB = sm + TM * K;   // [K][TN]
    int tid = threadIdx.x;
    int row0 = blockIdx.x * TM, n0 = blockIdx.y * TN;

    float4* sA4 = reinterpret_cast<float4*>(sA);
    for (int i = tid; i < TM * (K / 4); i += 256) {
        int kq = i % (K / 4), m = i / (K / 4);
        int row = row0 + m;
        float4 v = {0.f, 0.f, 0.f, 0.f};
        if (row < nrows) v = *reinterpret_cast<const float4*>(&X[(size_t)row * K + 4 * kq]);
        sA4[m * (K / 4) + kq] = v;
    }
    float4* sB4 = reinterpret_cast<float4*>(sB);
    for (int i = tid; i < K * (TN / 4); i += 256) {
        int nq = i % (TN / 4), k = i / (TN / 4);
        sB4[k * (TN / 4) + nq] =
            *reinterpret_cast<const float4*>(&WT[(size_t)k * N + n0 + 4 * nq]);
    }
    __syncthreads();

    int tx = tid % 16, ty = tid / 16;
    float c[4][4];
#pragma unroll
    for (int i = 0; i < 4; i++)
#pragma unroll
        for (int j = 0; j < 4; j++) c[i][j] = 0.f;

#pragma unroll 4
    for (int k = 0; k < K; k++) {
        float4 b4 = *reinterpret_cast<const float4*>(&sB[k * TN + tx * 4]);
        float a0 = sA[(ty * 4 + 0) * K + k];
        float a1 = sA[(ty * 4 + 1) * K + k];
        float a2 = sA[(ty * 4 + 2) * K + k];
        float a3 = sA[(ty * 4 + 3) * K + k];
        c[0][0] += a0 * b4.x; c[0][1] += a0 * b4.y; c[0][2] += a0 * b4.z; c[0][3] += a0 * b4.w;
        c[1][0] += a1 * b4.x; c[1][1] += a1 * b4.y; c[1][2] += a1 * b4.z; c[1][3] += a1 * b4.w;
        c[2][0] += a2 * b4.x; c[2][1] += a2 * b4.y; c[2][2] += a2 * b4.z; c[2][3] += a2 * b4.w;
        c[3][0] += a3 * b4.x; c[3][1] += a3 * b4.y; c[3][2] += a3 * b4.z; c[3][3] += a3 * b4.w;
    }

    float4 bb = *reinterpret_cast<const float4*>(&b[n0 + tx * 4]);
#pragma unroll
    for (int i = 0; i < 4; i++) {
        int row = row0 + ty * 4 + i;
        if (row < nrows) {
            float4 o;
            o.x = fmaxf(c[i][0] + bb.x, 0.f);
            o.y = fmaxf(c[i][1] + bb.y, 0.f);
            o.z = fmaxf(c[i][2] + bb.z, 0.f);
            o.w = fmaxf(c[i][3] + bb.w, 0.f);
            *reinterpret_cast<float4*>(&out[(size_t)row * N + n0 + tx * 4]) = o;
        }
    }
}

// c[k,j] = bih+bhh + sum_d q0[k,d]*(Wih[k,j,d] + Whh[k,j,d]); q0 inline from biases
__global__ void s2s_cvec(const float* __restrict__ Wih, const float* __restrict__ Whh,
                         const float* __restrict__ bih, const float* __restrict__ bhh,
                         float* __restrict__ c) {
    int k = blockIdx.y;
    int tid = threadIdx.x;
    int j = blockIdx.x * 256 + tid;
    __shared__ __align__(16) float sq[256];
    {
        const float* bi = bih + k * 1024;
        const float* bh = bhh + k * 1024;
        float gi = bi[tid] + bh[tid];
        float gg = bi[512 + tid] + bh[512 + tid];
        float go = bi[768 + tid] + bh[768 + tid];
        float cs = sigm(gi) * tanhf(gg);
        sq[tid] = sigm(go) * tanhf(cs);
    }
    __syncthreads();
    const float* wi = Wih + ((size_t)k * 1024 + j) * 512;
    const float* wh = Whh + ((size_t)k * 1024 + j) * 256;
    float acc = bih[k * 1024 + j] + bhh[k * 1024 + j];
    for (int d = 0; d < 256; d += 4) {
        float4 a = *reinterpret_cast<const float4*>(wi + d);
        float4 bq = *reinterpret_cast<const float4*>(wh + d);
        float4 s = *reinterpret_cast<const float4*>(&sq[d]);
        acc += (a.x + bq.x) * s.x + (a.y + bq.y) * s.y + (a.z + bq.z) * s.z + (a.w + bq.w) * s.w;
    }
    c[k * 1024 + j] = acc;
}

// ---------------- attention ----------------
// PASS 0: q0 inline from biases; writes r0.
// PASS 1: q1 = lstm(gates, bias-derived cs0) inline; writes ONLY the xg partial dot (atomicAdd).
template <int PASS>
__global__ void attn_kernel(const float* __restrict__ h4, const int* __restrict__ pn,
                            const float* __restrict__ gates, const float* __restrict__ bih,
                            const float* __restrict__ bhh, const float* __restrict__ Wg,
                            float* __restrict__ r0out, float* __restrict__ xg) {
    int p = blockIdx.x, k = blockIdx.y;
    extern __shared__ float smdyn[];
    float* sx = smdyn;
    float* sq = smdyn + 64 * 256;
    float* dots = sq + 256;
    int* spn = (int*)(dots + 64);
    int tid = threadIdx.x;

    {
        const float* bi = bih + k * 1024;
        const float* bh = bhh + k * 1024;
        float bgi = bi[tid] + bh[tid];
        float bgg = bi[512 + tid] + bh[512 + tid];
        float bgo = bi[768 + tid] + bh[768 + tid];
        float cs0 = sigm(bgi) * tanhf(bgg);
        if (PASS == 0) {
            sq[tid] = sigm(bgo) * tanhf(cs0);
        } else {
            const float* g = gates + ((size_t)(k * P_PATH + p)) * 1024;
            float gi = g[tid], gf = g[256 + tid], gg = g[512 + tid], go = g[768 + tid];
            float cs = sigm(gf) * cs0 + sigm(gi) * tanhf(gg);
            sq[tid] = sigm(go) * tanhf(cs);
        }
    }
    if (tid < 64) spn[tid] = pn[p * 64 + tid];
    __syncthreads();

    const float4* h4v = reinterpret_cast<const float4*>(h4);
    float4* sxv = reinterpret_cast<float4*>(sx);
    for (int i = tid; i < 64 * 64; i += 256) {
        int s = i >> 6, c = i & 63;
        sxv[i] = h4v[(size_t)spn[s] * 64 + c];
    }
    __syncthreads();

    int w = tid >> 5, lane = tid & 31;
    for (int s = w; s < 64; s += 8) {
        const float* xr = sx + s * 256;
        float part = 0.f;
#pragma unroll
        for (int m = 0; m < 8; m++) part += xr[lane + 32 * m] * sq[lane + 32 * m];
        for (int off = 16; off; off >>= 1) part += __shfl_down_sync(0xffffffffu, part, off);
        if (lane == 0) dots[s] = part;
    }
    __syncthreads();
    if (w == 0) {
        float a = dots[lane], b = dots[lane + 32];
        float mx = fmaxf(a, b);
        for (int off = 16; off; off >>= 1) mx = fmaxf(mx, __shfl_xor_sync(0xffffffffu, mx, off));
        float e0 = __expf(a - mx), e1 = __expf(b - mx);
        float sum = e0 + e1;
        for (int off = 16; off; off >>= 1) sum += __shfl_xor_sync(0xffffffffu, sum, off);
        float inv = 1.f / sum;
        dots[lane] = e0 * inv;
        dots[lane + 32] = e1 * inv;
    }
    __syncthreads();
    float acc = 0.f;
#pragma unroll 8
    for (int s = 0; s < 64; s++) acc += dots[s] * sx[s * 256 + tid];

    if (PASS == 0) {
        r0out[((size_t)k * P_PATH + p) * 256 + tid] = acc;
    } else {
        // xg partial: q1 . Wg[k, 0:256] + r1 . Wg[k, 256:512]
        float part = sq[tid] * Wg[k * 512 + tid] + acc * Wg[k * 512 + 256 + tid];
        __syncthreads();  // dots free for reuse
        for (int off = 16; off; off >>= 1) part += __shfl_xor_sync(0xffffffffu, part, off);
        if (lane == 0) dots[w] = part;
        __syncthreads();
        if (tid == 0) {
            float t = 0.f;
#pragma unroll
            for (int i = 0; i < 8; i++) t += dots[i];
            atomicAdd(&xg[p], t);
        }
    }
}

// ---------------- gates1 = c[k,:] + r0 @ Wih[:, D:2D]^T  (f32x2, 32-row tiles) ----------------
__global__ void gates_gemm(const float* __restrict__ r0, const float* __restrict__ Wih,
                           const float* __restrict__ c, float* __restrict__ gates) {
    constexpr int RT = 32;
    int ct = blockIdx.x, rt = blockIdx.y, k = blockIdx.z;
    __shared__ __align__(16) float sR[RT * 256];
    int tid = threadIdx.x;
    const float* rbase = r0 + ((size_t)k * P_PATH + rt * RT) * 256;
    for (int i = tid; i < RT * 256; i += 256) sR[i] = rbase[i];
    __syncthreads();
    int j = ct * 256 + tid;
    const ull* wrow = reinterpret_cast<const ull*>(Wih + ((size_t)k * 1024 + j) * 512 + 256);
    ull acc2[RT];
#pragma unroll
    for (int r = 0; r < RT; r++) acc2[r] = 0ull;
    for (int d = 0; d < 256; d += 4) {
        ull w01 = wrow[d / 2];
        ull w23 = wrow[d / 2 + 1];
#pragma unroll
        for (int r = 0; r < RT; r++) {
            const ull* sp = reinterpret_cast<const ull*>(&sR[r * 256]);
            ffma2(acc2[r], w01, sp[d / 2]);
            ffma2(acc2[r], w23, sp[d / 2 + 1]);
        }
    }
    float cj = c[k * 1024 + j];
#pragma unroll
    for (int r = 0; r < RT; r++)
        gates[((size_t)k * P_PATH + rt * RT + r) * 1024 + j] = hsum2(acc2[r]) + cj;
}

// ---------------- final MLP: xg+bg -> tanh 256 -> relu 64 -> sigmoid 1 ----------------
__global__ void final_kernel(const float* __restrict__ xg, const float* __restrict__ bg,
                             const float* __restrict__ Wl1, const float* __restrict__ bl1,
                             const float* __restrict__ Wl2, const float* __restrict__ bl2,
                             const float* __restrict__ Wl3, const float* __restrict__ bl3,
                             float* __restrict__ out) {
    __shared__ __align__(16) float sxg[512];
    __shared__ __align__(16) float sz1[256];
    __shared__ float sz2[64];
    int tid = threadIdx.x;
    float bgv = bg[0];
    sxg[tid] = xg[tid] + bgv;
    sxg[tid + 256] = xg[tid + 256] + bgv;
    __syncthreads();
    {
        float a = bl1[tid];
        const float* w = Wl1 + (size_t)tid * 512;
        for (int p = 0; p < 512; p += 4) {
            float4 w4 = *reinterpret_cast<const float4*>(w + p);
            float4 x4 = *reinterpret_cast<const float4*>(&sxg[p]);
            a += w4.x * x4.x + w4.y * x4.y + w4.z * x4.z + w4.w * x4.w;
        }
        sz1[tid] = tanhf(a);
    }
    __syncthreads();
    if (tid < 64) {
        float bacc = bl2[tid];
        const float* w2 = Wl2 + (size_t)tid * 256;
        for (int hh = 0; hh < 256; hh += 4) {
            float4 w4 = *reinterpret_cast<const float4*>(w2 + hh);
            float4 z4 = *reinterpret_cast<const float4*>(&sz1[hh]);
            bacc += w4.x * z4.x + w4.y * z4.y + w4.z * z4.z + w4.w * z4.w;
        }
        sz2[tid] = fmaxf(bacc, 0.f);
    }
    __syncthreads();
    if (tid == 0) {
        float cacc = bl3[0];
        for (int j = 0; j < 64; j++) cacc += sz2[j] * Wl3[j];
        out[0] = 1.f / (1.f + __expf(-cacc));
    }
}

// ---------------- host launcher ----------------
extern "C" void kernel_launch(void* const* d_in, const int* in_sizes, int n_in,
                              void* d_out, int out_size) {
    const float* h = (const float*)d_in[0];
    const int* src = (const int*)d_in[1];
    const int* dst = (const int*)d_in[2];
    const int* pn = (const int*)d_in[3];
    const float* W1 = (const float*)d_in[4];
    const float* b1 = (const float*)d_in[5];
    const float* W2 = (const float*)d_in[6];
    const float* b2 = (const float*)d_in[7];
    const float* W3 = (const float*)d_in[8];
    const float* b3 = (const float*)d_in[9];
    const float* W4 = (const float*)d_in[10];
    const float* b4 = (const float*)d_in[11];
    const float* Wih = (const float*)d_in[12];
    const float* Whh = (const float*)d_in[13];
    const float* bih = (const float*)d_in[14];
    const float* bhh = (const float*)d_in[15];
    const float* Wg = (const float*)d_in[16];
    const float* bg = (const float*)d_in[17];
    const float* Wl1 = (const float*)d_in[18];
    const float* bl1 = (const float*)d_in[19];
    const float* Wl2 = (const float*)d_in[20];
    const float* bl2 = (const float*)d_in[21];
    const float* Wl3 = (const float*)d_in[22];
    const float* bl3 = (const float*)d_in[23];
    int E = in_sizes[1];
    float* out = (float*)d_out;

    float *agg, *part, *h1, *h2, *h3, *h4, *w3t, *w4t, *cvec, *r0, *gates, *xg;
    int *deg, *off, *cur, *srcs;
    cudaGetSymbolAddress((void**)&agg, g_agg);
    cudaGetSymbolAddress((void**)&part, g_part);
    cudaGetSymbolAddress((void**)&h1, g_h1);
    cudaGetSymbolAddress((void**)&h2, g_h2);
    cudaGetSymbolAddress((void**)&h3, g_h3);
    cudaGetSymbolAddress((void**)&h4, g_h4);
    cudaGetSymbolAddress((void**)&w3t, g_w3t);
    cudaGetSymbolAddress((void**)&w4t, g_w4t);
    cudaGetSymbolAddress((void**)&cvec, g_c);
    cudaGetSymbolAddress((void**)&r0, g_r0);
    cudaGetSymbolAddress((void**)&gates, g_gates);
    cudaGetSymbolAddress((void**)&xg, g_xg);
    cudaGetSymbolAddress((void**)&deg, g_deg);
    cudaGetSymbolAddress((void**)&off, g_off);
    cudaGetSymbolAddress((void**)&cur, g_cur);
    cudaGetSymbolAddress((void**)&srcs, g_srcs);

    const int smem1 = (24 * 12 + 32 * 8) * 4;
    const int smem2 = (64 * 28 + 32 * 24) * 4;
    const int rt3_smem = (64 * 64 + 64 * 64) * 4;      // 32.8 KB
    const int rt4_smem = (64 * 128 + 128 * 64) * 4;    // 65.5 KB
    cudaFuncSetAttribute(gemm_rt<64, 128>, cudaFuncAttributeMaxDynamicSharedMemorySize,
                         rt3_smem);
    cudaFuncSetAttribute(gemm_rt<128, 256>, cudaFuncAttributeMaxDynamicSharedMemorySize,
                         rt4_smem);
    const int attn_smem = (64 * 256 + 256 + 64 + 64) * 4;
    cudaFuncSetAttribute(attn_kernel<0>, cudaFuncAttributeMaxDynamicSharedMemorySize, attn_smem);
    cudaFuncSetAttribute(attn_kernel<1>, cudaFuncAttributeMaxDynamicSharedMemorySize, attn_smem);

    // ---- prologue: memsets + W transposes (no deps) ----
    cudaMemsetAsync(deg, 0, NN * sizeof(int));
    cudaMemsetAsync(xg, 0, P_PATH * sizeof(float));
    wtrans<64, 128><<<(64 * 128 + 255) / 256, 256>>>(W3, w3t);
    wtrans<128, 256><<<(128 * 256 + 255) / 256, 256>>>(W4, w4t);

    // ---- CSR build ----
    hist_kernel<<<(E + 255) / 256, 256>>>(dst, deg, E);
    scan_kernel<<<1, 1024>>>(deg, off, cur);
    bucket_kernel<<<(E + 255) / 256, 256>>>(src, dst, cur, srcs, E);

    // ---- 4 GIN layers ----
    aggregate_sliced<8, 8><<<(NN * 2 * 8 + 255) / 256, 256>>>(h, off, srcs, part);
    combine_k<8, 8><<<(NN * 2 + 255) / 256, 256>>>(h, part, agg);
    gemm_relu<8, 24, 32, 256, 32><<<(NN + 31) / 32, 256, smem1>>>(agg, W1, b1, h1, NN);

    aggregate_sliced<24, 4><<<(NN * 6 * 4 + 255) / 256, 256>>>(h1, off, srcs, part);
    combine_k<24, 4><<<(NN * 6 + 255) / 256, 256>>>(h1, part, agg);
    gemm_relu<24, 64, 64, 256, 32><<<(NN + 31) / 32, 256, smem2>>>(agg, W2, b2, h2, NN);

    aggregate_k<64><<<(NN * 16 + 255) / 256, 256>>>(h2, off, srcs, agg);
    gemm_rt<64, 128><<<dim3((NN + 63) / 64, 2), 256, rt3_smem>>>(agg, w3t, b3, h3, NN);

    aggregate_k<128><<<(NN * 32 + 255) / 256, 256>>>(h3, off, srcs, agg);
    gemm_rt<128, 256><<<dim3((NN + 63) / 64, 4), 256, rt4_smem>>>(agg, w4t, b4, h4, NN);

    // ---- Set2Set ----
    attn_kernel<0><<<dim3(P_PATH, 3), 256, attn_smem>>>(h4, pn, nullptr, bih, bhh, Wg, r0, xg);
    s2s_cvec<<<dim3(4, 3), 256>>>(Wih, Whh, bih, bhh, cvec);
    gates_gemm<<<dim3(4, P_PATH / 32, 3), 256>>>(r0, Wih, cvec, gates);
    attn_kernel<1><<<dim3(P_PATH, 3), 256, attn_smem>>>(h4, pn, gates, bih, bhh, Wg, nullptr,
                                                        xg);

    final_kernel<<<1, 256>>>(xg, bg, Wl1, bl1, Wl2, bl2, Wl3, bl3, out);
}

// round 8
// speedup vs baseline: 1.6465x; 1.0552x over previous
#include <cuda_runtime.h>
#include <cuda_bf16.h>
#include <cstdint>

#define NN 20000
#define NE 640000
#define P_PATH 512
#define S_SUB 64
#define DHID 256
#define SCAN_B 79  // ceil(20000/256)

typedef unsigned long long ull;

// ---------------- scratch (static device globals; no allocation) ----------------
static __device__ __align__(16) float g_agg[NN * 128];
static __device__ __align__(16) float g_part[NN * 256];
static __device__ __align__(16) float g_h1[NN * 24];
static __device__ __align__(16) float g_h2[NN * 64];
static __device__ __align__(16) float g_h3[NN * 128];
static __device__ __align__(16) float g_h4[NN * 256];
static __device__ __align__(16) float g_w3t[64 * 128];   // W3^T [K=64][N=128]
static __device__ __align__(16) float g_w4t[128 * 256];  // W4^T [K=128][N=256]
static __device__ int g_deg[NN];
static __device__ int g_off[NN + 1];
static __device__ int g_cur[NN];
static __device__ int g_bsum[SCAN_B];
static __device__ int g_bpre[SCAN_B];
static __device__ int g_srcs[NE];
static __device__ float g_c[3 * 1024];
static __device__ __align__(16) float g_r0[3 * P_PATH * 256];
static __device__ __align__(16) float g_gates[3 * P_PATH * 1024];
static __device__ float g_xg[P_PATH];

__device__ __forceinline__ float sigm(float x) { return 1.f / (1.f + __expf(-x)); }

__device__ __forceinline__ void ffma2(ull& acc, ull a, ull b) {
    asm("fma.rn.f32x2 %0, %1, %2, %0;" : "+l"(acc) : "l"(a), "l"(b));
}
__device__ __forceinline__ float hsum2(ull v) {
    return __uint_as_float((unsigned)v) + __uint_as_float((unsigned)(v >> 32));
}

// ---------------- CSR build ----------------
__global__ void hist_kernel(const int* __restrict__ dst, int* __restrict__ deg, int E) {
    int e = blockIdx.x * blockDim.x + threadIdx.x;
    if (e < E) atomicAdd(&deg[dst[e]], 1);
}

// stage 1: per-block sums of deg
__global__ void blocksum_kernel(const int* __restrict__ deg, int* __restrict__ bsum) {
    __shared__ int sred[8];
    int i = blockIdx.x * 256 + threadIdx.x;
    int v = (i < NN) ? deg[i] : 0;
    for (int o = 16; o; o >>= 1) v += __shfl_down_sync(0xffffffffu, v, o);
    if ((threadIdx.x & 31) == 0) sred[threadIdx.x >> 5] = v;
    __syncthreads();
    if (threadIdx.x == 0) {
        int t = 0;
#pragma unroll
        for (int j = 0; j < 8; j++) t += sred[j];
        bsum[blockIdx.x] = t;
    }
}

// stage 2: exclusive scan of SCAN_B block sums (1 warp), writes off[NN]
__global__ void scan_bsums(const int* __restrict__ bsum, int* __restrict__ bpre,
                           int* __restrict__ off) {
    if (threadIdx.x == 0) {
        int acc = 0;
        for (int b = 0; b < SCAN_B; b++) {
            bpre[b] = acc;
            acc += bsum[b];
        }
        off[NN] = acc;
    }
}

// stage 3: block-local exclusive scan + block prefix -> off, cur
__global__ void write_off(const int* __restrict__ deg, const int* __restrict__ bpre,
                          int* __restrict__ off, int* __restrict__ cur) {
    __shared__ int sd[256];
    int t = threadIdx.x;
    int i = blockIdx.x * 256 + t;
    sd[t] = (i < NN) ? deg[i] : 0;
    __syncthreads();
    // inclusive log-scan
    for (int o = 1; o < 256; o <<= 1) {
        int v = (t >= o) ? sd[t - o] : 0;
        __syncthreads();
        sd[t] += v;
        __syncthreads();
    }
    if (i < NN) {
        int excl = bpre[blockIdx.x] + sd[t] - ((i < NN) ? deg[i] : 0);
        off[i] = excl;
        cur[i] = excl;
    }
}

__global__ void bucket_kernel(const int* __restrict__ src, const int* __restrict__ dst,
                              int* __restrict__ cur, int* __restrict__ srcs, int E) {
    int e = blockIdx.x * blockDim.x + threadIdx.x;
    if (e < E) {
        int p = atomicAdd(&cur[dst[e]], 1);
        srcs[p] = src[e];
    }
}

// ---------------- W transpose: WT[k][n] = W[n][k] ----------------
template <int K, int N>
__global__ void wtrans(const float* __restrict__ W, float* __restrict__ WT) {
    int i = blockIdx.x * 256 + threadIdx.x;
    if (i < K * N) {
        int n = i % N, k = i / N;
        WT[k * N + n] = W[n * K + k];
    }
}

// ---------------- direct gather aggregation (large D) ----------------
template <int D>
__global__ void aggregate_k(const float* __restrict__ h, const int* __restrict__ off,
                            const int* __restrict__ srcs, float* __restrict__ outp) {
    constexpr int C = D / 4;
    int idx = blockIdx.x * blockDim.x + threadIdx.x;
    if (idx >= NN * C) return;
    int node = idx / C;
    int c = idx - node * C;
    const float4* hp = reinterpret_cast<const float4*>(h);
    float4 acc = hp[(size_t)node * C + c];
    int s0 = off[node], s1 = off[node + 1];
#pragma unroll 8
    for (int j = s0; j < s1; j++) {
        int s = __ldg(&srcs[j]);
        float4 v = hp[(size_t)s * C + c];
        acc.x += v.x;
        acc.y += v.y;
        acc.z += v.z;
        acc.w += v.w;
    }
    reinterpret_cast<float4*>(outp)[idx] = acc;
}

// ---------------- sliced aggregation (small D) ----------------
template <int D, int NS>
__global__ void aggregate_sliced(const float* __restrict__ h, const int* __restrict__ off,
                                 const int* __restrict__ srcs, float* __restrict__ part) {
    constexpr int C = D / 4;
    int idx = blockIdx.x * blockDim.x + threadIdx.x;
    if (idx >= NN * C * NS) return;
    int slice = idx / (NN * C);
    int rem = idx - slice * NN * C;
    int node = rem / C;
    int c = rem - node * C;
    const float4* hp = reinterpret_cast<const float4*>(h);
    int s0 = off[node], s1 = off[node + 1];
    int len = s1 - s0;
    int a = s0 + (len * slice) / NS;
    int b = s0 + (len * (slice + 1)) / NS;
    float4 acc = {0.f, 0.f, 0.f, 0.f};
#pragma unroll 4
    for (int j = a; j < b; j++) {
        int s = __ldg(&srcs[j]);
        float4 v = hp[(size_t)s * C + c];
        acc.x += v.x;
        acc.y += v.y;
        acc.z += v.z;
        acc.w += v.w;
    }
    reinterpret_cast<float4*>(part)[idx] = acc;
}

template <int D, int NS>
__global__ void combine_k(const float* __restrict__ h, const float* __restrict__ part,
                          float* __restrict__ outp) {
    constexpr int C = D / 4;
    int idx = blockIdx.x * blockDim.x + threadIdx.x;
    if (idx >= NN * C) return;
    const float4* hp = reinterpret_cast<const float4*>(h);
    const float4* pp = reinterpret_cast<const float4*>(part);
    float4 acc = hp[idx];
#pragma unroll
    for (int s = 0; s < NS; s++) {
        float4 v = pp[(size_t)s * NN * C + idx];
        acc.x += v.x;
        acc.y += v.y;
        acc.z += v.z;
        acc.w += v.w;
    }
    reinterpret_cast<float4*>(outp)[idx] = acc;
}

// ---------------- small GIN GEMM (layers 1-2): out = relu(xin @ W^T + b) ----------------
template <int K, int N, int NP, int T, int RPB>
__global__ void gemm_relu(const float* __restrict__ xin, const float* __restrict__ W,
                          const float* __restrict__ b, float* __restrict__ out, int nrows) {
    constexpr int LDK = K + 4;
    constexpr int G = T / NP;
    constexpr int RPT = RPB / G;
    extern __shared__ float sm[];
    float* sW = sm;
    float* sR = sm + N * LDK;
    int tid = threadIdx.x;
    for (int i = tid; i < K * N; i += T) {
        int j = i / K, k = i - j * K;
        sW[j * LDK + k] = W[i];
    }
    int row0 = blockIdx.x * RPB;
    for (int i = tid; i < RPB * K; i += T) {
        int r = i / K, k = i - r * K;
        int row = row0 + r;
        sR[i] = (row < nrows) ? xin[(size_t)row * K + k] : 0.f;
    }
    __syncthreads();
    int j = tid % NP;
    int rg = tid / NP;
    if (j < N) {
        float acc[RPT];
#pragma unroll
        for (int t = 0; t < RPT; t++) acc[t] = 0.f;
        for (int k = 0; k < K; k += 4) {
            float4 w4 = *reinterpret_cast<const float4*>(&sW[j * LDK + k]);
#pragma unroll
            for (int t = 0; t < RPT; t++) {
                float4 s4 = *reinterpret_cast<const float4*>(&sR[(rg + t * G) * K + k]);
                acc[t] += s4.x * w4.x + s4.y * w4.y + s4.z * w4.z + s4.w * w4.w;
            }
        }
        float bj = b[j];
#pragma unroll
        for (int t = 0; t < RPT; t++) {
            int row = row0 + rg + t * G;
            if (row < nrows) out[(size_t)row * N + j] = fmaxf(acc[t] + bj, 0.f);
        }
    }
}

// ---------------- register-tiled GEMM (layers 3-4): out = relu(X @ W^T + b) ----------------
template <int K, int N>
__global__ void gemm_rt(const float* __restrict__ X, const float* __restrict__ WT,
                        const float* __restrict__ b, float* __restrict__ out, int nrows) {
    constexpr int TM = 64, TN = 64;
    extern __shared__ float sm[];
    float* sA = sm;           // [TM][K]
    float* sB = sm + TM * K;  // [K][TN]
    int tid = threadIdx.x;
    int row0 = blockIdx.x * TM, n0 = blockIdx.y * TN;

    float4* sA4 = reinterpret_cast<float4*>(sA);
    for (int i = tid; i < TM * (K / 4); i += 256) {
        int kq = i % (K / 4), m = i / (K / 4);
        int row = row0 + m;
        float4 v = {0.f, 0.f, 0.f, 0.f};
        if (row < nrows) v = *reinterpret_cast<const float4*>(&X[(size_t)row * K + 4 * kq]);
        sA4[m * (K / 4) + kq] = v;
    }
    float4* sB4 = reinterpret_cast<float4*>(sB);
    for (int i = tid; i < K * (TN / 4); i += 256) {
        int nq = i % (TN / 4), k = i / (TN / 4);
        sB4[k * (TN / 4) + nq] =
            *reinterpret_cast<const float4*>(&WT[(size_t)k * N + n0 + 4 * nq]);
    }
    __syncthreads();

    int tx = tid % 16, ty = tid / 16;
    float c[4][4];
#pragma unroll
    for (int i = 0; i < 4; i++)
#pragma unroll
        for (int j = 0; j < 4; j++) c[i][j] = 0.f;

#pragma unroll 4
    for (int k = 0; k < K; k++) {
        float4 b4 = *reinterpret_cast<const float4*>(&sB[k * TN + tx * 4]);
        float a0 = sA[(ty * 4 + 0) * K + k];
        float a1 = sA[(ty * 4 + 1) * K + k];
        float a2 = sA[(ty * 4 + 2) * K + k];
        float a3 = sA[(ty * 4 + 3) * K + k];
        c[0][0] += a0 * b4.x; c[0][1] += a0 * b4.y; c[0][2] += a0 * b4.z; c[0][3] += a0 * b4.w;
        c[1][0] += a1 * b4.x; c[1][1] += a1 * b4.y; c[1][2] += a1 * b4.z; c[1][3] += a1 * b4.w;
        c[2][0] += a2 * b4.x; c[2][1] += a2 * b4.y; c[2][2] += a2 * b4.z; c[2][3] += a2 * b4.w;
        c[3][0] += a3 * b4.x; c[3][1] += a3 * b4.y; c[3][2] += a3 * b4.z; c[3][3] += a3 * b4.w;
    }

    float4 bb = *reinterpret_cast<const float4*>(&b[n0 + tx * 4]);
#pragma unroll
    for (int i = 0; i < 4; i++) {
        int row = row0 + ty * 4 + i;
        if (row < nrows) {
            float4 o;
            o.x = fmaxf(c[i][0] + bb.x, 0.f);
            o.y = fmaxf(c[i][1] + bb.y, 0.f);
            o.z = fmaxf(c[i][2] + bb.z, 0.f);
            o.w = fmaxf(c[i][3] + bb.w, 0.f);
            *reinterpret_cast<float4*>(&out[(size_t)row * N + n0 + tx * 4]) = o;
        }
    }
}

// c[k,j] = bih+bhh + sum_d q0[k,d]*(Wih[k,j,d] + Whh[k,j,d]); q0 inline from biases
__global__ void s2s_cvec(const float* __restrict__ Wih, const float* __restrict__ Whh,
                         const float* __restrict__ bih, const float* __restrict__ bhh,
                         float* __restrict__ c) {
    int k = blockIdx.y;
    int tid = threadIdx.x;
    int j = blockIdx.x * 256 + tid;
    __shared__ __align__(16) float sq[256];
    {
        const float* bi = bih + k * 1024;
        const float* bh = bhh + k * 1024;
        float gi = bi[tid] + bh[tid];
        float gg = bi[512 + tid] + bh[512 + tid];
        float go = bi[768 + tid] + bh[768 + tid];
        float cs = sigm(gi) * tanhf(gg);
        sq[tid] = sigm(go) * tanhf(cs);
    }
    __syncthreads();
    const float* wi = Wih + ((size_t)k * 1024 + j) * 512;
    const float* wh = Whh + ((size_t)k * 1024 + j) * 256;
    float acc = bih[k * 1024 + j] + bhh[k * 1024 + j];
    for (int d = 0; d < 256; d += 4) {
        float4 a = *reinterpret_cast<const float4*>(wi + d);
        float4 bq = *reinterpret_cast<const float4*>(wh + d);
        float4 s = *reinterpret_cast<const float4*>(&sq[d]);
        acc += (a.x + bq.x) * s.x + (a.y + bq.y) * s.y + (a.z + bq.z) * s.z + (a.w + bq.w) * s.w;
    }
    c[k * 1024 + j] = acc;
}

// ---------------- attention ----------------
template <int PASS>
__global__ void attn_kernel(const float* __restrict__ h4, const int* __restrict__ pn,
                            const float* __restrict__ gates, const float* __restrict__ bih,
                            const float* __restrict__ bhh, const float* __restrict__ Wg,
                            float* __restrict__ r0out, float* __restrict__ xg) {
    int p = blockIdx.x, k = blockIdx.y;
    extern __shared__ float smdyn[];
    float* sx = smdyn;
    float* sq = smdyn + 64 * 256;
    float* dots = sq + 256;
    int* spn = (int*)(dots + 64);
    int tid = threadIdx.x;

    {
        const float* bi = bih + k * 1024;
        const float* bh = bhh + k * 1024;
        float bgi = bi[tid] + bh[tid];
        float bgg = bi[512 + tid] + bh[512 + tid];
        float bgo = bi[768 + tid] + bh[768 + tid];
        float cs0 = sigm(bgi) * tanhf(bgg);
        if (PASS == 0) {
            sq[tid] = sigm(bgo) * tanhf(cs0);
        } else {
            const float* g = gates + ((size_t)(k * P_PATH + p)) * 1024;
            float gi = g[tid], gf = g[256 + tid], gg = g[512 + tid], go = g[768 + tid];
            float cs = sigm(gf) * cs0 + sigm(gi) * tanhf(gg);
            sq[tid] = sigm(go) * tanhf(cs);
        }
    }
    if (tid < 64) spn[tid] = pn[p * 64 + tid];
    __syncthreads();

    const float4* h4v = reinterpret_cast<const float4*>(h4);
    float4* sxv = reinterpret_cast<float4*>(sx);
    for (int i = tid; i < 64 * 64; i += 256) {
        int s = i >> 6, c = i & 63;
        sxv[i] = h4v[(size_t)spn[s] * 64 + c];
    }
    __syncthreads();

    int w = tid >> 5, lane = tid & 31;
    for (int s = w; s < 64; s += 8) {
        const float* xr = sx + s * 256;
        float part = 0.f;
#pragma unroll
        for (int m = 0; m < 8; m++) part += xr[lane + 32 * m] * sq[lane + 32 * m];
        for (int off = 16; off; off >>= 1) part += __shfl_down_sync(0xffffffffu, part, off);
        if (lane == 0) dots[s] = part;
    }
    __syncthreads();
    if (w == 0) {
        float a = dots[lane], b = dots[lane + 32];
        float mx = fmaxf(a, b);
        for (int off = 16; off; off >>= 1) mx = fmaxf(mx, __shfl_xor_sync(0xffffffffu, mx, off));
        float e0 = __expf(a - mx), e1 = __expf(b - mx);
        float sum = e0 + e1;
        for (int off = 16; off; off >>= 1) sum += __shfl_xor_sync(0xffffffffu, sum, off);
        float inv = 1.f / sum;
        dots[lane] = e0 * inv;
        dots[lane + 32] = e1 * inv;
    }
    __syncthreads();
    float acc = 0.f;
#pragma unroll 8
    for (int s = 0; s < 64; s++) acc += dots[s] * sx[s * 256 + tid];

    if (PASS == 0) {
        r0out[((size_t)k * P_PATH + p) * 256 + tid] = acc;
    } else {
        float part = sq[tid] * Wg[k * 512 + tid] + acc * Wg[k * 512 + 256 + tid];
        __syncthreads();
        for (int off = 16; off; off >>= 1) part += __shfl_xor_sync(0xffffffffu, part, off);
        if (lane == 0) dots[w] = part;
        __syncthreads();
        if (tid == 0) {
            float t = 0.f;
#pragma unroll
            for (int i = 0; i < 8; i++) t += dots[i];
            atomicAdd(&xg[p], t);
        }
    }
}

// ---------------- gates1 = c[k,:] + r0 @ Wih[:, D:2D]^T  (f32x2, 32-row tiles) ----------------
__global__ void gates_gemm(const float* __restrict__ r0, const float* __restrict__ Wih,
                           const float* __restrict__ c, float* __restrict__ gates) {
    constexpr int RT = 32;
    int ct = blockIdx.x, rt = blockIdx.y, k = blockIdx.z;
    __shared__ __align__(16) float sR[RT * 256];
    int tid = threadIdx.x;
    const float* rbase = r0 + ((size_t)k * P_PATH + rt * RT) * 256;
    for (int i = tid; i < RT * 256; i += 256) sR[i] = rbase[i];
    __syncthreads();
    int j = ct * 256 + tid;
    const ull* wrow = reinterpret_cast<const ull*>(Wih + ((size_t)k * 1024 + j) * 512 + 256);
    ull acc2[RT];
#pragma unroll
    for (int r = 0; r < RT; r++) acc2[r] = 0ull;
    for (int d = 0; d < 256; d += 4) {
        ull w01 = wrow[d / 2];
        ull w23 = wrow[d / 2 + 1];
#pragma unroll
        for (int r = 0; r < RT; r++) {
            const ull* sp = reinterpret_cast<const ull*>(&sR[r * 256]);
            ffma2(acc2[r], w01, sp[d / 2]);
            ffma2(acc2[r], w23, sp[d / 2 + 1]);
        }
    }
    float cj = c[k * 1024 + j];
#pragma unroll
    for (int r = 0; r < RT; r++)
        gates[((size_t)k * P_PATH + rt * RT + r) * 1024 + j] = hsum2(acc2[r]) + cj;
}

// ---------------- final MLP ----------------
__global__ void final_kernel(const float* __restrict__ xg, const float* __restrict__ bg,
                             const float* __restrict__ Wl1, const float* __restrict__ bl1,
                             const float* __restrict__ Wl2, const float* __restrict__ bl2,
                             const float* __restrict__ Wl3, const float* __restrict__ bl3,
                             float* __restrict__ out) {
    __shared__ __align__(16) float sxg[512];
    __shared__ __align__(16) float sz1[256];
    __shared__ float sz2[64];
    int tid = threadIdx.x;
    float bgv = bg[0];
    sxg[tid] = xg[tid] + bgv;
    sxg[tid + 256] = xg[tid + 256] + bgv;
    __syncthreads();
    {
        float a = bl1[tid];
        const float* w = Wl1 + (size_t)tid * 512;
        for (int p = 0; p < 512; p += 4) {
            float4 w4 = *reinterpret_cast<const float4*>(w + p);
            float4 x4 = *reinterpret_cast<const float4*>(&sxg[p]);
            a += w4.x * x4.x + w4.y * x4.y + w4.z * x4.z + w4.w * x4.w;
        }
        sz1[tid] = tanhf(a);
    }
    __syncthreads();
    if (tid < 64) {
        float bacc = bl2[tid];
        const float* w2 = Wl2 + (size_t)tid * 256;
        for (int hh = 0; hh < 256; hh += 4) {
            float4 w4 = *reinterpret_cast<const float4*>(w2 + hh);
            float4 z4 = *reinterpret_cast<const float4*>(&sz1[hh]);
            bacc += w4.x * z4.x + w4.y * z4.y + w4.z * z4.z + w4.w * z4.w;
        }
        sz2[tid] = fmaxf(bacc, 0.f);
    }
    __syncthreads();
    if (tid == 0) {
        float cacc = bl3[0];
        for (int j = 0; j < 64; j++) cacc += sz2[j] * Wl3[j];
        out[0] = 1.f / (1.f + __expf(-cacc));
    }
}

// ---------------- host launcher ----------------
extern "C" void kernel_launch(void* const* d_in, const int* in_sizes, int n_in,
                              void* d_out, int out_size) {
    const float* h = (const float*)d_in[0];
    const int* src = (const int*)d_in[1];
    const int* dst = (const int*)d_in[2];
    const int* pn = (const int*)d_in[3];
    const float* W1 = (const float*)d_in[4];
    const float* b1 = (const float*)d_in[5];
    const float* W2 = (const float*)d_in[6];
    const float* b2 = (const float*)d_in[7];
    const float* W3 = (const float*)d_in[8];
    const float* b3 = (const float*)d_in[9];
    const float* W4 = (const float*)d_in[10];
    const float* b4 = (const float*)d_in[11];
    const float* Wih = (const float*)d_in[12];
    const float* Whh = (const float*)d_in[13];
    const float* bih = (const float*)d_in[14];
    const float* bhh = (const float*)d_in[15];
    const float* Wg = (const float*)d_in[16];
    const float* bg = (const float*)d_in[17];
    const float* Wl1 = (const float*)d_in[18];
    const float* bl1 = (const float*)d_in[19];
    const float* Wl2 = (const float*)d_in[20];
    const float* bl2 = (const float*)d_in[21];
    const float* Wl3 = (const float*)d_in[22];
    const float* bl3 = (const float*)d_in[23];
    int E = in_sizes[1];
    float* out = (float*)d_out;

    float *agg, *part, *h1, *h2, *h3, *h4, *w3t, *w4t, *cvec, *r0, *gates, *xg;
    int *deg, *off, *cur, *srcs, *bsum, *bpre;
    cudaGetSymbolAddress((void**)&agg, g_agg);
    cudaGetSymbolAddress((void**)&part, g_part);
    cudaGetSymbolAddress((void**)&h1, g_h1);
    cudaGetSymbolAddress((void**)&h2, g_h2);
    cudaGetSymbolAddress((void**)&h3, g_h3);
    cudaGetSymbolAddress((void**)&h4, g_h4);
    cudaGetSymbolAddress((void**)&w3t, g_w3t);
    cudaGetSymbolAddress((void**)&w4t, g_w4t);
    cudaGetSymbolAddress((void**)&cvec, g_c);
    cudaGetSymbolAddress((void**)&r0, g_r0);
    cudaGetSymbolAddress((void**)&gates, g_gates);
    cudaGetSymbolAddress((void**)&xg, g_xg);
    cudaGetSymbolAddress((void**)&deg, g_deg);
    cudaGetSymbolAddress((void**)&off, g_off);
    cudaGetSymbolAddress((void**)&cur, g_cur);
    cudaGetSymbolAddress((void**)&srcs, g_srcs);
    cudaGetSymbolAddress((void**)&bsum, g_bsum);
    cudaGetSymbolAddress((void**)&bpre, g_bpre);

    const int smem1 = (24 * 12 + 32 * 8) * 4;
    const int smem2 = (64 * 28 + 32 * 24) * 4;
    const int rt3_smem = (64 * 64 + 64 * 64) * 4;    // 32.8 KB
    const int rt4_smem = (64 * 128 + 128 * 64) * 4;  // 65.5 KB
    cudaFuncSetAttribute(gemm_rt<64, 128>, cudaFuncAttributeMaxDynamicSharedMemorySize,
                         rt3_smem);
    cudaFuncSetAttribute(gemm_rt<128, 256>, cudaFuncAttributeMaxDynamicSharedMemorySize,
                         rt4_smem);
    const int attn_smem = (64 * 256 + 256 + 64 + 64) * 4;
    cudaFuncSetAttribute(attn_kernel<0>, cudaFuncAttributeMaxDynamicSharedMemorySize, attn_smem);
    cudaFuncSetAttribute(attn_kernel<1>, cudaFuncAttributeMaxDynamicSharedMemorySize, attn_smem);

    // ---- prologue ----
    cudaMemsetAsync(deg, 0, NN * sizeof(int));
    cudaMemsetAsync(xg, 0, P_PATH * sizeof(float));
    wtrans<64, 128><<<(64 * 128 + 255) / 256, 256>>>(W3, w3t);
    wtrans<128, 256><<<(128 * 256 + 255) / 256, 256>>>(W4, w4t);

    // ---- CSR build (3-stage parallel scan) ----
    hist_kernel<<<(E + 255) / 256, 256>>>(dst, deg, E);
    blocksum_kernel<<<SCAN_B, 256>>>(deg, bsum);
    scan_bsums<<<1, 32>>>(bsum, bpre, off);
    write_off<<<SCAN_B, 256>>>(deg, bpre, off, cur);
    bucket_kernel<<<(E + 255) / 256, 256>>>(src, dst, cur, srcs, E);

    // ---- 4 GIN layers ----
    aggregate_sliced<8, 8><<<(NN * 2 * 8 + 255) / 256, 256>>>(h, off, srcs, part);
    combine_k<8, 8><<<(NN * 2 + 255) / 256, 256>>>(h, part, agg);
    gemm_relu<8, 24, 32, 256, 32><<<(NN + 31) / 32, 256, smem1>>>(agg, W1, b1, h1, NN);

    aggregate_sliced<24, 4><<<(NN * 6 * 4 + 255) / 256, 256>>>(h1, off, srcs, part);
    combine_k<24, 4><<<(NN * 6 + 255) / 256, 256>>>(h1, part, agg);
    gemm_relu<24, 64, 64, 256, 32><<<(NN + 31) / 32, 256, smem2>>>(agg, W2, b2, h2, NN);

    aggregate_k<64><<<(NN * 16 + 255) / 256, 256>>>(h2, off, srcs, agg);
    gemm_rt<64, 128><<<dim3((NN + 63) / 64, 2), 256, rt3_smem>>>(agg, w3t, b3, h3, NN);

    aggregate_k<128><<<(NN * 32 + 255) / 256, 256>>>(h3, off, srcs, agg);
    gemm_rt<128, 256><<<dim3((NN + 63) / 64, 4), 256, rt4_smem>>>(agg, w4t, b4, h4, NN);

    // ---- Set2Set ----
    attn_kernel<0><<<dim3(P_PATH, 3), 256, attn_smem>>>(h4, pn, nullptr, bih, bhh, Wg, r0, xg);
    s2s_cvec<<<dim3(4, 3), 256>>>(Wih, Whh, bih, bhh, cvec);
    gates_gemm<<<dim3(4, P_PATH / 32, 3), 256>>>(r0, Wih, cvec, gates);
    attn_kernel<1><<<dim3(P_PATH, 3), 256, attn_smem>>>(h4, pn, gates, bih, bhh, Wg, nullptr,
                                                        xg);

    final_kernel<<<1, 256>>>(xg, bg, Wl1, bl1, Wl2, bl2, Wl3, bl3, out);
}

// round 9
// speedup vs baseline: 1.6523x; 1.0035x over previous
#include <cuda_runtime.h>
#include <cuda_bf16.h>
#include <cstdint>

#define NN 20000
#define NE 640000
#define P_PATH 512
#define S_SUB 64
#define DHID 256
#define SCAN_B 79  // ceil(20000/256)

typedef unsigned long long ull;

// ---------------- scratch (static device globals; no allocation) ----------------
static __device__ __align__(16) float g_agg[NN * 128];
static __device__ __align__(16) float g_part[NN * 256];
static __device__ __align__(16) float g_h1[NN * 24];
static __device__ __align__(16) float g_h2[NN * 64];
static __device__ __align__(16) float g_h3[NN * 128];
static __device__ __align__(16) float g_h4[NN * 256];
static __device__ __align__(16) float g_w3t[64 * 128];   // W3^T [K=64][N=128]
static __device__ __align__(16) float g_w4t[128 * 256];  // W4^T [K=128][N=256]
static __device__ int g_deg[NN];
static __device__ int g_off[NN + 1];
static __device__ int g_cur[NN];
static __device__ int g_bsum[SCAN_B];
static __device__ int g_bpre[SCAN_B];
static __device__ int g_ticket;
static __device__ int g_srcs[NE];
static __device__ float g_c[3 * 1024];
static __device__ __align__(16) float g_r0[3 * P_PATH * 256];
static __device__ __align__(16) float g_gates[3 * P_PATH * 1024];
static __device__ float g_xg[P_PATH];

__device__ __forceinline__ float sigm(float x) { return 1.f / (1.f + __expf(-x)); }

__device__ __forceinline__ void ffma2(ull& acc, ull a, ull b) {
    asm("fma.rn.f32x2 %0, %1, %2, %0;" : "+l"(acc) : "l"(a), "l"(b));
}
__device__ __forceinline__ float hsum2(ull v) {
    return __uint_as_float((unsigned)v) + __uint_as_float((unsigned)(v >> 32));
}

// ---------------- CSR build ----------------
__global__ void hist_kernel(const int* __restrict__ dst, int* __restrict__ deg, int E) {
    int e = blockIdx.x * blockDim.x + threadIdx.x;
    if (e < E) atomicAdd(&deg[dst[e]], 1);
}

// per-block sums + (last block) serial scan of SCAN_B partials
__global__ void blocksum_scan(const int* __restrict__ deg, int* __restrict__ bsum,
                              int* __restrict__ bpre, int* __restrict__ off,
                              int* __restrict__ ticket) {
    __shared__ int sred[8];
    int i = blockIdx.x * 256 + threadIdx.x;
    int v = (i < NN) ? deg[i] : 0;
    for (int o = 16; o; o >>= 1) v += __shfl_down_sync(0xffffffffu, v, o);
    if ((threadIdx.x & 31) == 0) sred[threadIdx.x >> 5] = v;
    __syncthreads();
    if (threadIdx.x == 0) {
        int t = 0;
#pragma unroll
        for (int j = 0; j < 8; j++) t += sred[j];
        bsum[blockIdx.x] = t;
        __threadfence();
        int tk = atomicAdd(ticket, 1);
        if (tk == SCAN_B - 1) {
            int acc = 0;
            for (int b = 0; b < SCAN_B; b++) {
                bpre[b] = acc;
                acc += bsum[b];
            }
            off[NN] = acc;
            *ticket = 0;  // reset for next graph replay
        }
    }
}

// block-local exclusive scan + block prefix -> off, cur
__global__ void write_off(const int* __restrict__ deg, const int* __restrict__ bpre,
                          int* __restrict__ off, int* __restrict__ cur) {
    __shared__ int sd[256];
    int t = threadIdx.x;
    int i = blockIdx.x * 256 + t;
    int dv = (i < NN) ? deg[i] : 0;
    sd[t] = dv;
    __syncthreads();
    for (int o = 1; o < 256; o <<= 1) {
        int v = (t >= o) ? sd[t - o] : 0;
        __syncthreads();
        sd[t] += v;
        __syncthreads();
    }
    if (i < NN) {
        int excl = bpre[blockIdx.x] + sd[t] - dv;
        off[i] = excl;
        cur[i] = excl;
    }
}

__global__ void bucket_kernel(const int* __restrict__ src, const int* __restrict__ dst,
                              int* __restrict__ cur, int* __restrict__ srcs, int E) {
    int e = blockIdx.x * blockDim.x + threadIdx.x;
    if (e < E) {
        int p = atomicAdd(&cur[dst[e]], 1);
        srcs[p] = src[e];
    }
}

// ---------------- merged W transposes ----------------
__global__ void wtrans_all(const float* __restrict__ W3, float* __restrict__ w3t,
                           const float* __restrict__ W4, float* __restrict__ w4t) {
    int i = blockIdx.x * 256 + threadIdx.x;
    if (i < 64 * 128) {
        int n = i % 128, k = i / 128;
        w3t[k * 128 + n] = W3[n * 64 + k];
    } else {
        int j = i - 64 * 128;
        if (j < 128 * 256) {
            int n = j % 256, k = j / 256;
            w4t[k * 256 + n] = W4[n * 128 + k];
        }
    }
}

// ---------------- direct gather aggregation (large D) ----------------
template <int D>
__global__ void aggregate_k(const float* __restrict__ h, const int* __restrict__ off,
                            const int* __restrict__ srcs, float* __restrict__ outp) {
    constexpr int C = D / 4;
    int idx = blockIdx.x * blockDim.x + threadIdx.x;
    if (idx >= NN * C) return;
    int node = idx / C;
    int c = idx - node * C;
    const float4* hp = reinterpret_cast<const float4*>(h);
    float4 acc = hp[(size_t)node * C + c];
    int s0 = off[node], s1 = off[node + 1];
#pragma unroll 8
    for (int j = s0; j < s1; j++) {
        int s = __ldg(&srcs[j]);
        float4 v = hp[(size_t)s * C + c];
        acc.x += v.x;
        acc.y += v.y;
        acc.z += v.z;
        acc.w += v.w;
    }
    reinterpret_cast<float4*>(outp)[idx] = acc;
}

// ---------------- sliced aggregation (small D) ----------------
template <int D, int NS>
__global__ void aggregate_sliced(const float* __restrict__ h, const int* __restrict__ off,
                                 const int* __restrict__ srcs, float* __restrict__ part) {
    constexpr int C = D / 4;
    int idx = blockIdx.x * blockDim.x + threadIdx.x;
    if (idx >= NN * C * NS) return;
    int slice = idx / (NN * C);
    int rem = idx - slice * NN * C;
    int node = rem / C;
    int c = rem - node * C;
    const float4* hp = reinterpret_cast<const float4*>(h);
    int s0 = off[node], s1 = off[node + 1];
    int len = s1 - s0;
    int a = s0 + (len * slice) / NS;
    int b = s0 + (len * (slice + 1)) / NS;
    float4 acc = {0.f, 0.f, 0.f, 0.f};
#pragma unroll 4
    for (int j = a; j < b; j++) {
        int s = __ldg(&srcs[j]);
        float4 v = hp[(size_t)s * C + c];
        acc.x += v.x;
        acc.y += v.y;
        acc.z += v.z;
        acc.w += v.w;
    }
    reinterpret_cast<float4*>(part)[idx] = acc;
}

// ---------------- small GIN GEMM (layers 1-2): out = relu((xin + sum part) @ W^T + b) ------
template <int K, int N, int NP, int T, int RPB, int NSLICE>
__global__ void gemm_relu(const float* __restrict__ xin, const float* __restrict__ part,
                          const float* __restrict__ W, const float* __restrict__ b,
                          float* __restrict__ out, int nrows) {
    constexpr int LDK = K + 4;
    constexpr int G = T / NP;
    constexpr int RPT = RPB / G;
    extern __shared__ float sm[];
    float* sW = sm;
    float* sR = sm + N * LDK;
    int tid = threadIdx.x;
    for (int i = tid; i < K * N; i += T) {
        int j = i / K, k = i - j * K;
        sW[j * LDK + k] = W[i];
    }
    int row0 = blockIdx.x * RPB;
    for (int i = tid; i < RPB * K; i += T) {
        int r = i / K, k = i - r * K;
        int row = row0 + r;
        float v = 0.f;
        if (row < nrows) {
            v = xin[(size_t)row * K + k];
#pragma unroll
            for (int s = 0; s < NSLICE; s++) v += part[((size_t)s * NN + row) * K + k];
        }
        sR[i] = v;
    }
    __syncthreads();
    int j = tid % NP;
    int rg = tid / NP;
    if (j < N) {
        float acc[RPT];
#pragma unroll
        for (int t = 0; t < RPT; t++) acc[t] = 0.f;
        for (int k = 0; k < K; k += 4) {
            float4 w4 = *reinterpret_cast<const float4*>(&sW[j * LDK + k]);
#pragma unroll
            for (int t = 0; t < RPT; t++) {
                float4 s4 = *reinterpret_cast<const float4*>(&sR[(rg + t * G) * K + k]);
                acc[t] += s4.x * w4.x + s4.y * w4.y + s4.z * w4.z + s4.w * w4.w;
            }
        }
        float bj = b[j];
#pragma unroll
        for (int t = 0; t < RPT; t++) {
            int row = row0 + rg + t * G;
            if (row < nrows) out[(size_t)row * N + j] = fmaxf(acc[t] + bj, 0.f);
        }
    }
}

// ---------------- register-tiled GEMM (layers 3-4), k-paired f32x2 ----------------
// X:[nrows][K], WT:[K][N]. Tile 64m x 64n, 256 threads, thread = 4m x 4n (n strided by 16).
// B staged transposed [n][k] with row stride K+2 floats -> conflict-free LDS.64.
template <int K, int N>
__global__ void gemm_rt(const float* __restrict__ X, const float* __restrict__ WT,
                        const float* __restrict__ b, float* __restrict__ out, int nrows) {
    constexpr int TM = 64, TN = 64;
    constexpr int RSF = K + 2;  // sBt row stride (floats); (K+2)/2 = odd ull stride
    extern __shared__ float sm[];
    float* sA = sm;             // [TM][K]
    float* sBt = sm + TM * K;   // [TN][RSF]
    int tid = threadIdx.x;
    int row0 = blockIdx.x * TM, n0 = blockIdx.y * TN;

    float4* sA4 = reinterpret_cast<float4*>(sA);
    for (int i = tid; i < TM * (K / 4); i += 256) {
        int kq = i % (K / 4), m = i / (K / 4);
        int row = row0 + m;
        float4 v = {0.f, 0.f, 0.f, 0.f};
        if (row < nrows) v = *reinterpret_cast<const float4*>(&X[(size_t)row * K + 4 * kq]);
        sA4[m * (K / 4) + kq] = v;
    }
    for (int i = tid; i < K * (TN / 4); i += 256) {
        int nq = i % (TN / 4), k = i / (TN / 4);
        float4 v = *reinterpret_cast<const float4*>(&WT[(size_t)k * N + n0 + 4 * nq]);
        sBt[(4 * nq + 0) * RSF + k] = v.x;
        sBt[(4 * nq + 1) * RSF + k] = v.y;
        sBt[(4 * nq + 2) * RSF + k] = v.z;
        sBt[(4 * nq + 3) * RSF + k] = v.w;
    }
    __syncthreads();

    int tx = tid % 16, ty = tid / 16;
    ull c2[4][4];
#pragma unroll
    for (int i = 0; i < 4; i++)
#pragma unroll
        for (int j = 0; j < 4; j++) c2[i][j] = 0ull;

#pragma unroll 8
    for (int kp = 0; kp < K / 2; kp++) {
        ull av[4], bv[4];
#pragma unroll
        for (int i = 0; i < 4; i++)
            av[i] = *reinterpret_cast<const ull*>(&sA[(ty * 4 + i) * K + 2 * kp]);
#pragma unroll
        for (int jj = 0; jj < 4; jj++)
            bv[jj] = *reinterpret_cast<const ull*>(&sBt[(tx + 16 * jj) * RSF + 2 * kp]);
#pragma unroll
        for (int i = 0; i < 4; i++)
#pragma unroll
            for (int jj = 0; jj < 4; jj++) ffma2(c2[i][jj], av[i], bv[jj]);
    }

#pragma unroll
    for (int i = 0; i < 4; i++) {
        int row = row0 + ty * 4 + i;
        if (row < nrows) {
#pragma unroll
            for (int jj = 0; jj < 4; jj++) {
                int n = n0 + tx + 16 * jj;
                out[(size_t)row * N + n] = fmaxf(hsum2(c2[i][jj]) + b[n], 0.f);
            }
        }
    }
}

// c[k,j] = bih+bhh + sum_d q0[k,d]*(Wih[k,j,d] + Whh[k,j,d]); q0 inline from biases
__global__ void s2s_cvec(const float* __restrict__ Wih, const float* __restrict__ Whh,
                         const float* __restrict__ bih, const float* __restrict__ bhh,
                         float* __restrict__ c) {
    int k = blockIdx.y;
    int tid = threadIdx.x;
    int j = blockIdx.x * 256 + tid;
    __shared__ __align__(16) float sq[256];
    {
        const float* bi = bih + k * 1024;
        const float* bh = bhh + k * 1024;
        float gi = bi[tid] + bh[tid];
        float gg = bi[512 + tid] + bh[512 + tid];
        float go = bi[768 + tid] + bh[768 + tid];
        float cs = sigm(gi) * tanhf(gg);
        sq[tid] = sigm(go) * tanhf(cs);
    }
    __syncthreads();
    const float* wi = Wih + ((size_t)k * 1024 + j) * 512;
    const float* wh = Whh + ((size_t)k * 1024 + j) * 256;
    float acc = bih[k * 1024 + j] + bhh[k * 1024 + j];
    for (int d = 0; d < 256; d += 4) {
        float4 a = *reinterpret_cast<const float4*>(wi + d);
        float4 bq = *reinterpret_cast<const float4*>(wh + d);
        float4 s = *reinterpret_cast<const float4*>(&sq[d]);
        acc += (a.x + bq.x) * s.x + (a.y + bq.y) * s.y + (a.z + bq.z) * s.z + (a.w + bq.w) * s.w;
    }
    c[k * 1024 + j] = acc;
}

// ---------------- attention (fused gather; PASS1 also fuses LSTM + xg partial) ------------
template <int PASS>
__global__ void attn_kernel(const float* __restrict__ h4, const int* __restrict__ pn,
                            const float* __restrict__ gates, const float* __restrict__ bih,
                            const float* __restrict__ bhh, const float* __restrict__ Wg,
                            float* __restrict__ r0out, float* __restrict__ xg) {
    int p = blockIdx.x, k = blockIdx.y;
    extern __shared__ float smdyn[];
    float* sx = smdyn;
    float* sq = smdyn + 64 * 256;
    float* dots = sq + 256;
    int* spn = (int*)(dots + 64);
    int tid = threadIdx.x;

    {
        const float* bi = bih + k * 1024;
        const float* bh = bhh + k * 1024;
        float bgi = bi[tid] + bh[tid];
        float bgg = bi[512 + tid] + bh[512 + tid];
        float bgo = bi[768 + tid] + bh[768 + tid];
        float cs0 = sigm(bgi) * tanhf(bgg);
        if (PASS == 0) {
            sq[tid] = sigm(bgo) * tanhf(cs0);
        } else {
            const float* g = gates + ((size_t)(k * P_PATH + p)) * 1024;
            float gi = g[tid], gf = g[256 + tid], gg = g[512 + tid], go = g[768 + tid];
            float cs = sigm(gf) * cs0 + sigm(gi) * tanhf(gg);
            sq[tid] = sigm(go) * tanhf(cs);
        }
    }
    if (tid < 64) spn[tid] = pn[p * 64 + tid];
    __syncthreads();

    const float4* h4v = reinterpret_cast<const float4*>(h4);
    float4* sxv = reinterpret_cast<float4*>(sx);
    for (int i = tid; i < 64 * 64; i += 256) {
        int s = i >> 6, c = i & 63;
        sxv[i] = h4v[(size_t)spn[s] * 64 + c];
    }
    __syncthreads();

    int w = tid >> 5, lane = tid & 31;
    for (int s = w; s < 64; s += 8) {
        const float* xr = sx + s * 256;
        float part = 0.f;
#pragma unroll
        for (int m = 0; m < 8; m++) part += xr[lane + 32 * m] * sq[lane + 32 * m];
        for (int off = 16; off; off >>= 1) part += __shfl_down_sync(0xffffffffu, part, off);
        if (lane == 0) dots[s] = part;
    }
    __syncthreads();
    if (w == 0) {
        float a = dots[lane], b = dots[lane + 32];
        float mx = fmaxf(a, b);
        for (int off = 16; off; off >>= 1) mx = fmaxf(mx, __shfl_xor_sync(0xffffffffu, mx, off));
        float e0 = __expf(a - mx), e1 = __expf(b - mx);
        float sum = e0 + e1;
        for (int off = 16; off; off >>= 1) sum += __shfl_xor_sync(0xffffffffu, sum, off);
        float inv = 1.f / sum;
        dots[lane] = e0 * inv;
        dots[lane + 32] = e1 * inv;
    }
    __syncthreads();
    float acc = 0.f;
#pragma unroll 8
    for (int s = 0; s < 64; s++) acc += dots[s] * sx[s * 256 + tid];

    if (PASS == 0) {
        r0out[((size_t)k * P_PATH + p) * 256 + tid] = acc;
    } else {
        float part = sq[tid] * Wg[k * 512 + tid] + acc * Wg[k * 512 + 256 + tid];
        __syncthreads();
        for (int off = 16; off; off >>= 1) part += __shfl_xor_sync(0xffffffffu, part, off);
        if (lane == 0) dots[w] = part;
        __syncthreads();
        if (tid == 0) {
            float t = 0.f;
#pragma unroll
            for (int i = 0; i < 8; i++) t += dots[i];
            atomicAdd(&xg[p], t);
        }
    }
}

// ---------------- gates1 = c[k,:] + r0 @ Wih[:, D:2D]^T  (f32x2, 32-row tiles) -----------
__global__ void gates_gemm(const float* __restrict__ r0, const float* __restrict__ Wih,
                           const float* __restrict__ c, float* __restrict__ gates) {
    constexpr int RT = 32;
    int ct = blockIdx.x, rt = blockIdx.y, k = blockIdx.z;
    __shared__ __align__(16) float sR[RT * 256];
    int tid = threadIdx.x;
    const float* rbase = r0 + ((size_t)k * P_PATH + rt * RT) * 256;
    for (int i = tid; i < RT * 256; i += 256) sR[i] = rbase[i];
    __syncthreads();
    int j = ct * 256 + tid;
    const ull* wrow = reinterpret_cast<const ull*>(Wih + ((size_t)k * 1024 + j) * 512 + 256);
    ull acc2[RT];
#pragma unroll
    for (int r = 0; r < RT; r++) acc2[r] = 0ull;
    for (int d = 0; d < 256; d += 4) {
        ull w01 = wrow[d / 2];
        ull w23 = wrow[d / 2 + 1];
#pragma unroll
        for (int r = 0; r < RT; r++) {
            const ull* sp = reinterpret_cast<const ull*>(&sR[r * 256]);
            ffma2(acc2[r], w01, sp[d / 2]);
            ffma2(acc2[r], w23, sp[d / 2 + 1]);
        }
    }
    float cj = c[k * 1024 + j];
#pragma unroll
    for (int r = 0; r < RT; r++)
        gates[((size_t)k * P_PATH + rt * RT + r) * 1024 + j] = hsum2(acc2[r]) + cj;
}

// ---------------- final MLP ----------------
__global__ void final_kernel(const float* __restrict__ xg, const float* __restrict__ bg,
                             const float* __restrict__ Wl1, const float* __restrict__ bl1,
                             const float* __restrict__ Wl2, const float* __restrict__ bl2,
                             const float* __restrict__ Wl3, const float* __restrict__ bl3,
                             float* __restrict__ out) {
    __shared__ __align__(16) float sxg[512];
    __shared__ __align__(16) float sz1[256];
    __shared__ float sz2[64];
    int tid = threadIdx.x;
    float bgv = bg[0];
    sxg[tid] = xg[tid] + bgv;
    sxg[tid + 256] = xg[tid + 256] + bgv;
    __syncthreads();
    {
        float a = bl1[tid];
        const float* w = Wl1 + (size_t)tid * 512;
        for (int p = 0; p < 512; p += 4) {
            float4 w4 = *reinterpret_cast<const float4*>(w + p);
            float4 x4 = *reinterpret_cast<const float4*>(&sxg[p]);
            a += w4.x * x4.x + w4.y * x4.y + w4.z * x4.z + w4.w * x4.w;
        }
        sz1[tid] = tanhf(a);
    }
    __syncthreads();
    if (tid < 64) {
        float bacc = bl2[tid];
        const float* w2 = Wl2 + (size_t)tid * 256;
        for (int hh = 0; hh < 256; hh += 4) {
            float4 w4 = *reinterpret_cast<const float4*>(w2 + hh);
            float4 z4 = *reinterpret_cast<const float4*>(&sz1[hh]);
            bacc += w4.x * z4.x + w4.y * z4.y + w4.z * z4.z + w4.w * z4.w;
        }
        sz2[tid] = fmaxf(bacc, 0.f);
    }
    __syncthreads();
    if (tid == 0) {
        float cacc = bl3[0];
        for (int j = 0; j < 64; j++) cacc += sz2[j] * Wl3[j];
        out[0] = 1.f / (1.f + __expf(-cacc));
    }
}

// ---------------- host launcher ----------------
extern "C" void kernel_launch(void* const* d_in, const int* in_sizes, int n_in,
                              void* d_out, int out_size) {
    const float* h = (const float*)d_in[0];
    const int* src = (const int*)d_in[1];
    const int* dst = (const int*)d_in[2];
    const int* pn = (const int*)d_in[3];
    const float* W1 = (const float*)d_in[4];
    const float* b1 = (const float*)d_in[5];
    const float* W2 = (const float*)d_in[6];
    const float* b2 = (const float*)d_in[7];
    const float* W3 = (const float*)d_in[8];
    const float* b3 = (const float*)d_in[9];
    const float* W4 = (const float*)d_in[10];
    const float* b4 = (const float*)d_in[11];
    const float* Wih = (const float*)d_in[12];
    const float* Whh = (const float*)d_in[13];
    const float* bih = (const float*)d_in[14];
    const float* bhh = (const float*)d_in[15];
    const float* Wg = (const float*)d_in[16];
    const float* bg = (const float*)d_in[17];
    const float* Wl1 = (const float*)d_in[18];
    const float* bl1 = (const float*)d_in[19];
    const float* Wl2 = (const float*)d_in[20];
    const float* bl2 = (const float*)d_in[21];
    const float* Wl3 = (const float*)d_in[22];
    const float* bl3 = (const float*)d_in[23];
    int E = in_sizes[1];
    float* out = (float*)d_out;

    float *agg, *part, *h1, *h2, *h3, *h4, *w3t, *w4t, *cvec, *r0, *gates, *xg;
    int *deg, *off, *cur, *srcs, *bsum, *bpre, *ticket;
    cudaGetSymbolAddress((void**)&agg, g_agg);
    cudaGetSymbolAddress((void**)&part, g_part);
    cudaGetSymbolAddress((void**)&h1, g_h1);
    cudaGetSymbolAddress((void**)&h2, g_h2);
    cudaGetSymbolAddress((void**)&h3, g_h3);
    cudaGetSymbolAddress((void**)&h4, g_h4);
    cudaGetSymbolAddress((void**)&w3t, g_w3t);
    cudaGetSymbolAddress((void**)&w4t, g_w4t);
    cudaGetSymbolAddress((void**)&cvec, g_c);
    cudaGetSymbolAddress((void**)&r0, g_r0);
    cudaGetSymbolAddress((void**)&gates, g_gates);
    cudaGetSymbolAddress((void**)&xg, g_xg);
    cudaGetSymbolAddress((void**)&deg, g_deg);
    cudaGetSymbolAddress((void**)&off, g_off);
    cudaGetSymbolAddress((void**)&cur, g_cur);
    cudaGetSymbolAddress((void**)&srcs, g_srcs);
    cudaGetSymbolAddress((void**)&bsum, g_bsum);
    cudaGetSymbolAddress((void**)&bpre, g_bpre);
    cudaGetSymbolAddress((void**)&ticket, g_ticket);

    const int smem1 = (24 * 12 + 32 * 8) * 4;
    const int smem2 = (64 * 28 + 32 * 24) * 4;
    const int rt3_smem = (64 * 64 + 64 * 66) * 4;     // sA + sBt(stride 66)  ~33.3 KB
    const int rt4_smem = (64 * 128 + 64 * 130) * 4;   // ~66.0 KB
    cudaFuncSetAttribute(gemm_rt<64, 128>, cudaFuncAttributeMaxDynamicSharedMemorySize,
                         rt3_smem);
    cudaFuncSetAttribute(gemm_rt<128, 256>, cudaFuncAttributeMaxDynamicSharedMemorySize,
                         rt4_smem);
    const int attn_smem = (64 * 256 + 256 + 64 + 64) * 4;
    cudaFuncSetAttribute(attn_kernel<0>, cudaFuncAttributeMaxDynamicSharedMemorySize, attn_smem);
    cudaFuncSetAttribute(attn_kernel<1>, cudaFuncAttributeMaxDynamicSharedMemorySize, attn_smem);

    // ---- CSR build (bucket_kernel lands in ncu slot 6) ----
    cudaMemsetAsync(deg, 0, NN * sizeof(int));                                   // 1
    wtrans_all<<<(64 * 128 + 128 * 256 + 255) / 256, 256>>>(W3, w3t, W4, w4t);   // 2
    hist_kernel<<<(E + 255) / 256, 256>>>(dst, deg, E);                          // 3
    blocksum_scan<<<SCAN_B, 256>>>(deg, bsum, bpre, off, ticket);                // 4
    write_off<<<SCAN_B, 256>>>(deg, bpre, off, cur);                             // 5
    bucket_kernel<<<(E + 255) / 256, 256>>>(src, dst, cur, srcs, E);             // 6

    // ---- 4 GIN layers ----
    aggregate_sliced<8, 8><<<(NN * 2 * 8 + 255) / 256, 256>>>(h, off, srcs, part);
    gemm_relu<8, 24, 32, 256, 32, 8><<<(NN + 31) / 32, 256, smem1>>>(h, part, W1, b1, h1, NN);

    aggregate_sliced<24, 4><<<(NN * 6 * 4 + 255) / 256, 256>>>(h1, off, srcs, part);
    gemm_relu<24, 64, 64, 256, 32, 4><<<(NN + 31) / 32, 256, smem2>>>(h1, part, W2, b2, h2, NN);

    aggregate_k<64><<<(NN * 16 + 255) / 256, 256>>>(h2, off, srcs, agg);
    gemm_rt<64, 128><<<dim3((NN + 63) / 64, 2), 256, rt3_smem>>>(agg, w3t, b3, h3, NN);

    aggregate_k<128><<<(NN * 32 + 255) / 256, 256>>>(h3, off, srcs, agg);
    gemm_rt<128, 256><<<dim3((NN + 63) / 64, 4), 256, rt4_smem>>>(agg, w4t, b4, h4, NN);

    // ---- Set2Set ----
    cudaMemsetAsync(xg, 0, P_PATH * sizeof(float));
    attn_kernel<0><<<dim3(P_PATH, 3), 256, attn_smem>>>(h4, pn, nullptr, bih, bhh, Wg, r0, xg);
    s2s_cvec<<<dim3(4, 3), 256>>>(Wih, Whh, bih, bhh, cvec);
    gates_gemm<<<dim3(4, P_PATH / 32, 3), 256>>>(r0, Wih, cvec, gates);
    attn_kernel<1><<<dim3(P_PATH, 3), 256, attn_smem>>>(h4, pn, gates, bih, bhh, Wg, nullptr,
                                                        xg);

    final_kernel<<<1, 256>>>(xg, bg, Wl1, bl1, Wl2, bl2, Wl3, bl3, out);
}